// round 4
// baseline (speedup 1.0000x reference)
#include <cuda_runtime.h>
#include <cuda_bf16.h>
#include <cstdint>
#include <math_constants.h>

#define NN 100000
#define EE 600000
#define DD 128
#define EPSLN 1e-5f
#define PADH 136   // smem row stride in halves (272B -> conflict-free ldmatrix)

// ---------------- scratch (device globals) -------------------------------------
__device__ float g_y[3L * NN * DD];
__device__ float g_hin[(size_t)NN * DD];
__device__ float g_s0[(size_t)NN * DD];
__device__ float g_s1[(size_t)NN * DD];
__device__ float g_m0[(size_t)NN * DD];
__device__ float g_m1[(size_t)NN * DD];
__device__ float g_slast[(size_t)NN * DD];
__device__ float g_mean[(size_t)NN * DD];
__device__ float g_max[(size_t)NN * DD];
__device__ float g_stats[2 * 3 * DD];
__device__ int   g_deg[NN];
__device__ int   g_rowptr[NN + 1];
__device__ int   g_cursor[NN];
__device__ int   g_ssrc[EE];
__device__ int   g_bsums[256];
__device__ __nv_bfloat16 g_wpre[27L * 32768];   // per matrix: hi[f*128+d] 16384, lo 16384

// ---------------- helpers ------------------------------------------------------
__device__ __forceinline__ uint32_t smem_u32(const void* p) {
    uint32_t a;
    asm("{ .reg .u64 t; cvta.to.shared.u64 t, %1; cvt.u32.u64 %0, t; }" : "=r"(a) : "l"(p));
    return a;
}
__device__ __forceinline__ uint32_t pk(__nv_bfloat16 a, __nv_bfloat16 b) {
    return (uint32_t)__bfloat16_as_ushort(a) | ((uint32_t)__bfloat16_as_ushort(b) << 16);
}
__device__ __forceinline__ void ldsm_x4(uint32_t& r0, uint32_t& r1, uint32_t& r2, uint32_t& r3,
                                        uint32_t addr) {
    asm volatile("ldmatrix.sync.aligned.m8n8.x4.shared.b16 {%0, %1, %2, %3}, [%4];"
                 : "=r"(r0), "=r"(r1), "=r"(r2), "=r"(r3) : "r"(addr));
}
__device__ __forceinline__ void mma16816(float* c, const uint32_t* a, const uint32_t* b) {
    asm volatile(
        "mma.sync.aligned.m16n8k16.row.col.f32.bf16.bf16.f32 "
        "{%0, %1, %2, %3}, {%4, %5, %6, %7}, {%8, %9}, {%0, %1, %2, %3};"
        : "+f"(c[0]), "+f"(c[1]), "+f"(c[2]), "+f"(c[3])
        : "r"(a[0]), "r"(a[1]), "r"(a[2]), "r"(a[3]), "r"(b[0]), "r"(b[1]));
}

// ---------------- weight prep: W[d][f] fp32 -> [f][k=d] bf16 hi/lo --------------
__global__ void k_wprep(const float* __restrict__ W, __nv_bfloat16* __restrict__ out) {
    int m = blockIdx.x;
    const float* src = W + (size_t)m * 16384;
    __nv_bfloat16* ohi = out + (size_t)m * 32768;
    __nv_bfloat16* olo = ohi + 16384;
    for (int idx = threadIdx.x; idx < 16384; idx += blockDim.x) {
        int d = idx >> 7, f = idx & 127;
        float v = src[idx];
        __nv_bfloat16 h = __float2bfloat16(v);
        __nv_bfloat16 l = __float2bfloat16(v - __bfloat162float(h));
        ohi[f * 128 + d] = h;
        olo[f * 128 + d] = l;
    }
}

// ---------------- bf16-split tensor GEMM + fused column stats -------------------
// 256 threads, 8 warps 4x2, warp tile 32x64, accumulate 3 bf16 passes in fp32.
#define SMEM_MMA (4 * 128 * PADH * 2 + 1024)

__global__ __launch_bounds__(256, 1) void k_gemm_mma(
    const float* __restrict__ x0, const float* __restrict__ x1, const float* __restrict__ x2,
    const __nv_bfloat16* __restrict__ wpre, const float* __restrict__ bias,
    float* __restrict__ Y, float* __restrict__ stats, int n, size_t ystride, int catmode)
{
    extern __shared__ char sm[];
    __nv_bfloat16* Ahi = (__nv_bfloat16*)sm;
    __nv_bfloat16* Alo = Ahi + 128 * PADH;
    __nv_bfloat16* Bhi = Alo + 128 * PADH;
    __nv_bfloat16* Blo = Bhi + 128 * PADH;
    float* ssum = (float*)(Blo + 128 * PADH);
    float* ssq  = ssum + 128;

    int tid = threadIdx.x;
    int wid = tid >> 5, lane = tid & 31;
    int wm_ = wid >> 1, wn_ = wid & 1;
    int kcand = catmode ? 0 : blockIdx.z;
    int nchunk = catmode ? 3 : 1;
    int row0 = blockIdx.x * 128;
    float* Yk = Y + (size_t)kcand * ystride;
    const float* bk = bias + kcand * DD;
    int so = kcand * DD;

    if (tid < 128) { ssum[tid] = 0.f; ssq[tid] = 0.f; }

    float c[2][8][4];
    #pragma unroll
    for (int i = 0; i < 2; i++)
        #pragma unroll
        for (int j = 0; j < 8; j++)
            #pragma unroll
            for (int q = 0; q < 4; q++) c[i][j][q] = 0.f;

    // lane-dependent ldmatrix offsets
    int a_row = wm_ * 32 + (lane & 15);
    int a_k8 = (lane >> 4) * 8;
    int b_f = wn_ * 64 + ((lane >> 4) << 3) + (lane & 7);
    int b_k8 = ((lane >> 3) & 1) * 8;
    uint32_t uAhi = smem_u32(Ahi), uAlo = smem_u32(Alo);
    uint32_t uBhi = smem_u32(Bhi), uBlo = smem_u32(Blo);

    for (int ch = 0; ch < nchunk; ch++) {
        const float* X = catmode ? (ch == 0 ? x0 : (ch == 1 ? x1 : x2))
                                 : (kcand == 0 ? x0 : (kcand == 1 ? x1 : x2));
        const __nv_bfloat16* wm = wpre + (size_t)(catmode ? ch : kcand) * 32768;

        if (ch > 0) __syncthreads();   // prior mma reads done before refill

        // B copy (pre-transposed, contiguous rows) -> padded smem
        for (int i = tid; i < 2048; i += 256) {
            int f = i >> 4, seg = i & 15;
            uint4 h = ((const uint4*)wm)[i];
            uint4 l = ((const uint4*)(wm + 16384))[i];
            *(uint4*)(Bhi + f * PADH + seg * 8) = h;
            *(uint4*)(Blo + f * PADH + seg * 8) = l;
        }
        // A convert fp32 -> bf16 hi/lo
        {
            int row = tid >> 1, sg = tid & 1;
            int gr = row0 + row;
            __nv_bfloat16* dh = Ahi + row * PADH + sg * 64;
            __nv_bfloat16* dl = Alo + row * PADH + sg * 64;
            #pragma unroll
            for (int q = 0; q < 16; q++) {
                float4 v = (gr < n) ? *(const float4*)(X + (size_t)gr * DD + sg * 64 + q * 4)
                                    : make_float4(0.f, 0.f, 0.f, 0.f);
                __nv_bfloat16 h0 = __float2bfloat16(v.x), h1 = __float2bfloat16(v.y);
                __nv_bfloat16 h2 = __float2bfloat16(v.z), h3 = __float2bfloat16(v.w);
                __nv_bfloat16 l0 = __float2bfloat16(v.x - __bfloat162float(h0));
                __nv_bfloat16 l1 = __float2bfloat16(v.y - __bfloat162float(h1));
                __nv_bfloat16 l2 = __float2bfloat16(v.z - __bfloat162float(h2));
                __nv_bfloat16 l3 = __float2bfloat16(v.w - __bfloat162float(h3));
                *(uint2*)(dh + q * 4) = make_uint2(pk(h0, h1), pk(h2, h3));
                *(uint2*)(dl + q * 4) = make_uint2(pk(l0, l1), pk(l2, l3));
            }
        }
        __syncthreads();

        // 3 bf16 passes: hi*hi, hi*lo, lo*hi
        #pragma unroll
        for (int seg = 0; seg < 3; seg++) {
            uint32_t Ab = (seg < 2) ? uAhi : uAlo;
            uint32_t Bb = (seg == 1) ? uBlo : uBhi;
            #pragma unroll
            for (int k = 0; k < 8; k++) {
                uint32_t a[2][4];
                #pragma unroll
                for (int mt = 0; mt < 2; mt++) {
                    uint32_t addr = Ab + (uint32_t)(((a_row + mt * 16) * PADH + k * 16 + a_k8) * 2);
                    ldsm_x4(a[mt][0], a[mt][1], a[mt][2], a[mt][3], addr);
                }
                uint32_t b[4][4];
                #pragma unroll
                for (int p = 0; p < 4; p++) {
                    uint32_t addr = Bb + (uint32_t)(((b_f + p * 16) * PADH + k * 16 + b_k8) * 2);
                    ldsm_x4(b[p][0], b[p][1], b[p][2], b[p][3], addr);
                }
                #pragma unroll
                for (int mt = 0; mt < 2; mt++)
                    #pragma unroll
                    for (int nt = 0; nt < 8; nt++)
                        mma16816(c[mt][nt], a[mt], &b[nt >> 1][(nt & 1) * 2]);
            }
        }
    }

    // ---------------- epilogue: bias, store Y, fused column stats ---------------
    int erow = lane >> 2, ecp = lane & 3;
    float2 bb[8];
    #pragma unroll
    for (int nt = 0; nt < 8; nt++)
        bb[nt] = *(const float2*)(bk + wn_ * 64 + nt * 8 + ecp * 2);

    float lsum[16], lsq[16];
    #pragma unroll
    for (int j = 0; j < 16; j++) { lsum[j] = 0.f; lsq[j] = 0.f; }

    __syncthreads();   // ssum/ssq zero visible; all mma done

    #pragma unroll
    for (int mt = 0; mt < 2; mt++) {
        int r0g = row0 + wm_ * 32 + mt * 16 + erow;
        int r1g = r0g + 8;
        #pragma unroll
        for (int nt = 0; nt < 8; nt++) {
            int cbase = wn_ * 64 + nt * 8 + ecp * 2;
            float v00 = c[mt][nt][0] + bb[nt].x;
            float v01 = c[mt][nt][1] + bb[nt].y;
            float v10 = c[mt][nt][2] + bb[nt].x;
            float v11 = c[mt][nt][3] + bb[nt].y;
            if (r0g < n) {
                *(float2*)(Yk + (size_t)r0g * DD + cbase) = make_float2(v00, v01);
                lsum[nt * 2]     += v00; lsq[nt * 2]     += v00 * v00;
                lsum[nt * 2 + 1] += v01; lsq[nt * 2 + 1] += v01 * v01;
            }
            if (r1g < n) {
                *(float2*)(Yk + (size_t)r1g * DD + cbase) = make_float2(v10, v11);
                lsum[nt * 2]     += v10; lsq[nt * 2]     += v10 * v10;
                lsum[nt * 2 + 1] += v11; lsq[nt * 2 + 1] += v11 * v11;
            }
        }
    }
    #pragma unroll
    for (int nt = 0; nt < 8; nt++) {
        int cbase = wn_ * 64 + nt * 8 + ecp * 2;
        atomicAdd(&ssum[cbase],     lsum[nt * 2]);
        atomicAdd(&ssq[cbase],      lsq[nt * 2]);
        atomicAdd(&ssum[cbase + 1], lsum[nt * 2 + 1]);
        atomicAdd(&ssq[cbase + 1],  lsq[nt * 2 + 1]);
    }
    __syncthreads();
    if (tid < 128) {
        atomicAdd(&stats[so + tid], ssum[tid]);
        atomicAdd(&stats[3 * DD + so + tid], ssq[tid]);
    }
}

// ---------------- CSR build ---------------------------------------------------
__global__ void k_hist(const int* __restrict__ dst, int* deg, int e) {
    int i = blockIdx.x * blockDim.x + threadIdx.x;
    if (i < e) atomicAdd(&deg[dst[i]], 1);
}
__global__ void k_scan_block(const int* __restrict__ deg, int* incl, int* bsums, int n) {
    __shared__ int sh[1024];
    int i = blockIdx.x * 1024 + threadIdx.x;
    int v = (i < n) ? deg[i] : 0;
    sh[threadIdx.x] = v;
    __syncthreads();
    for (int off = 1; off < 1024; off <<= 1) {
        int t = (threadIdx.x >= off) ? sh[threadIdx.x - off] : 0;
        __syncthreads();
        sh[threadIdx.x] += t;
        __syncthreads();
    }
    if (i < n) incl[i] = sh[threadIdx.x];
    if (threadIdx.x == 1023) bsums[blockIdx.x] = sh[1023];
}
__global__ void k_scan_sums(int* bsums, int nb) {
    if (threadIdx.x == 0 && blockIdx.x == 0) {
        int run = 0;
        for (int i = 0; i < nb; i++) { int t = bsums[i]; bsums[i] = run; run += t; }
    }
}
__global__ void k_scan_fin(const int* __restrict__ deg, const int* __restrict__ incl,
                           const int* __restrict__ bsums, int* rowptr, int* cursor, int n, int e) {
    int i = blockIdx.x * blockDim.x + threadIdx.x;
    if (i < n) {
        int ex = incl[i] - deg[i] + bsums[i >> 10];
        rowptr[i] = ex;
        cursor[i] = ex;
        if (i == n - 1) rowptr[n] = e;
    }
}
__global__ void k_scatter(const int* __restrict__ src, const int* __restrict__ dst,
                          int* cursor, int* ssrc, int e) {
    int i = blockIdx.x * blockDim.x + threadIdx.x;
    if (i < e) {
        int p = atomicAdd(&cursor[dst[i]], 1);
        ssrc[p] = src[i];
    }
}

// ---------------- graph aggregation (mean + max), warp per node ---------------
__global__ void k_agg(const float* __restrict__ h, const int* __restrict__ rowptr,
                      const int* __restrict__ ssrc, float* __restrict__ meanout,
                      float* __restrict__ maxout, int n) {
    int warp = (blockIdx.x * blockDim.x + threadIdx.x) >> 5;
    int lane = threadIdx.x & 31;
    if (warp >= n) return;
    int beg = rowptr[warp], end = rowptr[warp + 1];
    float4 s  = make_float4(0.f, 0.f, 0.f, 0.f);
    float4 mx = make_float4(-CUDART_INF_F, -CUDART_INF_F, -CUDART_INF_F, -CUDART_INF_F);
    for (int i = beg; i < end; i++) {
        int src = ssrc[i];
        float4 v = ((const float4*)(h + (size_t)src * DD))[lane];
        s.x += v.x; s.y += v.y; s.z += v.z; s.w += v.w;
        mx.x = fmaxf(mx.x, v.x); mx.y = fmaxf(mx.y, v.y);
        mx.z = fmaxf(mx.z, v.z); mx.w = fmaxf(mx.w, v.w);
    }
    int deg = end - beg;
    float inv = 1.0f / (float)max(deg, 1);
    float4 mo = make_float4(s.x * inv, s.y * inv, s.z * inv, s.w * inv);
    float4 xo = (deg > 0) ? mx : make_float4(0.f, 0.f, 0.f, 0.f);
    ((float4*)(meanout + (size_t)warp * DD))[lane] = mo;
    ((float4*)(maxout  + (size_t)warp * DD))[lane] = xo;
}

// ---------------- elementwise pre-candidates ----------------------------------
__global__ void k_pre(const float* __restrict__ a, const float* __restrict__ b,
                      float* __restrict__ p1, float* __restrict__ p2, int total) {
    int i = blockIdx.x * blockDim.x + threadIdx.x;
    if (i < total) {
        float x = a[i], y = b[i];
        p1[i] = x - y;
        p2[i] = x * y;
    }
}

// ---------------- mixed epilogue: normalize + relu + weighted k-sum -----------
__global__ void k_combine(const float* __restrict__ y, const float* __restrict__ stats,
                          const float* __restrict__ wrow, const float* __restrict__ gg,
                          const float* __restrict__ be, float* __restrict__ out,
                          int n, int accum) {
    int idx = blockIdx.x * blockDim.x + threadIdx.x;
    int total = n * DD;
    if (idx >= total) return;
    int d = idx & (DD - 1);
    float fn = (float)n;
    float acc = 0.f;
    #pragma unroll
    for (int k = 0; k < 3; k++) {
        float mu  = stats[k * DD + d] / fn;
        float var = stats[3 * DD + k * DD + d] / fn - mu * mu;
        float rs  = rsqrtf(var + EPSLN);
        float v = y[(size_t)k * n * DD + idx];
        float t = (v - mu) * rs * gg[k * DD + d] + be[k * DD + d];
        t = fmaxf(t, 0.f);
        acc += wrow[k] * t;
    }
    out[idx] = accum ? (out[idx] + acc) : acc;
}

// ---------------- final column-norm + relu ------------------------------------
__global__ void k_finalnorm(const float* __restrict__ h, const float* __restrict__ stats,
                            const float* __restrict__ gc, const float* __restrict__ bec,
                            float* __restrict__ out, int n) {
    int idx = blockIdx.x * blockDim.x + threadIdx.x;
    int total = n * DD;
    if (idx >= total) return;
    int d = idx & (DD - 1);
    float fn = (float)n;
    float mu  = stats[d] / fn;
    float var = stats[3 * DD + d] / fn - mu * mu;
    float rs  = rsqrtf(var + EPSLN);
    float v = (h[idx] - mu) * rs * gc[d] + bec[d];
    out[idx] = fmaxf(v, 0.f);
}

// ---------------- host orchestration ------------------------------------------
extern "C" void kernel_launch(void* const* d_in, const int* in_sizes, int n_in,
                              void* d_out, int out_size) {
    const float* src_emb = (const float*)d_in[0];
    const float* hr      = (const float*)d_in[1];
    const int*   esrc    = (const int*)d_in[2];
    const int*   edst    = (const int*)d_in[3];
    const float* w_zero  = (const float*)d_in[4];
    const float* w_first = (const float*)d_in[5];
    const float* w_mid   = (const float*)d_in[6];
    const float* w_last  = (const float*)d_in[7];
    const float* W_zero  = (const float*)d_in[8];
    const float* b_zero  = (const float*)d_in[9];
    const float* g_zeroP = (const float*)d_in[10];
    const float* be_zero = (const float*)d_in[11];
    const float* W_first = (const float*)d_in[12];
    const float* b_first = (const float*)d_in[13];
    const float* g_firstP= (const float*)d_in[14];
    const float* be_first= (const float*)d_in[15];
    const float* W_mid   = (const float*)d_in[16];
    const float* b_mid   = (const float*)d_in[17];
    const float* g_midP  = (const float*)d_in[18];
    const float* be_mid  = (const float*)d_in[19];
    const float* W_last  = (const float*)d_in[20];
    const float* b_last  = (const float*)d_in[21];
    const float* g_lastP = (const float*)d_in[22];
    const float* be_last = (const float*)d_in[23];
    const float* W_cat   = (const float*)d_in[24];
    const float* b_cat   = (const float*)d_in[25];
    const float* g_cat   = (const float*)d_in[26];
    const float* be_cat  = (const float*)d_in[27];

    int n = in_sizes[0] / DD;
    int e = in_sizes[2];

    float *yb, *hin, *s0, *s1, *m0, *m1, *sl, *mean, *mx, *stats;
    int *deg, *rowptr, *cursor, *ssrc, *bsums;
    __nv_bfloat16* wpre;
    cudaGetSymbolAddress((void**)&yb, g_y);
    cudaGetSymbolAddress((void**)&hin, g_hin);
    cudaGetSymbolAddress((void**)&s0, g_s0);
    cudaGetSymbolAddress((void**)&s1, g_s1);
    cudaGetSymbolAddress((void**)&m0, g_m0);
    cudaGetSymbolAddress((void**)&m1, g_m1);
    cudaGetSymbolAddress((void**)&sl, g_slast);
    cudaGetSymbolAddress((void**)&mean, g_mean);
    cudaGetSymbolAddress((void**)&mx, g_max);
    cudaGetSymbolAddress((void**)&stats, g_stats);
    cudaGetSymbolAddress((void**)&deg, g_deg);
    cudaGetSymbolAddress((void**)&rowptr, g_rowptr);
    cudaGetSymbolAddress((void**)&cursor, g_cursor);
    cudaGetSymbolAddress((void**)&ssrc, g_ssrc);
    cudaGetSymbolAddress((void**)&bsums, g_bsums);
    cudaGetSymbolAddress((void**)&wpre, g_wpre);

    cudaFuncSetAttribute(k_gemm_mma, cudaFuncAttributeMaxDynamicSharedMemorySize, SMEM_MMA);

    int total = n * DD;
    size_t ystride = (size_t)n * DD;
    int gtiles = (n + 127) / 128;
    int ew_grid = (total + 255) / 256;
    int agg_grid = (n + 7) / 8;
    int eb = (e + 255) / 256;
    int nb1024 = (n + 1023) / 1024;

    // ---- weight prep ----
    k_wprep<<<3, 256>>>(W_zero,  wpre + 0L  * 32768);
    k_wprep<<<9, 256>>>(W_first, wpre + 3L  * 32768);
    k_wprep<<<6, 256>>>(W_mid,   wpre + 12L * 32768);
    k_wprep<<<6, 256>>>(W_last,  wpre + 18L * 32768);
    k_wprep<<<3, 256>>>(W_cat,   wpre + 24L * 32768);

    // ---- CSR build ----
    cudaMemsetAsync(deg, 0, (size_t)n * sizeof(int));
    k_hist<<<eb, 256>>>(edst, deg, e);
    k_scan_block<<<nb1024, 1024>>>(deg, cursor, bsums, n);
    k_scan_sums<<<1, 32>>>(bsums, nb1024);
    k_scan_fin<<<(n + 255) / 256, 256>>>(deg, cursor, bsums, rowptr, cursor, n, e);
    k_scatter<<<eb, 256>>>(esrc, edst, cursor, ssrc, e);

    auto run_mixed = [&](const float* x0, const float* x1, const float* x2,
                         int opmat, const float* B, const float* G, const float* BE,
                         const float* wrow, float* out, int accum) {
        cudaMemsetAsync(stats, 0, 2 * 3 * DD * sizeof(float));
        k_gemm_mma<<<dim3(gtiles, 1, 3), 256, SMEM_MMA>>>(
            x0, x1, x2, wpre + (size_t)opmat * 32768, B, yb, stats, n, ystride, 0);
        k_combine<<<ew_grid, 256>>>(yb, stats, wrow, G, BE, out, n, accum);
    };

    // ---- zero op ----
    k_pre<<<ew_grid, 256>>>(src_emb, hr, mean, mx, total);
    run_mixed(src_emb, mean, mx, 0, b_zero, g_zeroP, be_zero, w_zero, hin, 0);

    // ---- first ops ----
    k_agg<<<agg_grid, 256>>>(hin, rowptr, ssrc, mean, mx, n);
    run_mixed(hin, mean, mx, 3, b_first + 0 * 3 * DD, g_firstP + 0 * 3 * DD,
              be_first + 0 * 3 * DD, w_first + 0 * 3, s0, 0);
    run_mixed(hin, mean, mx, 6, b_first + 1 * 3 * DD, g_firstP + 1 * 3 * DD,
              be_first + 1 * 3 * DD, w_first + 1 * 3, s1, 0);
    k_agg<<<agg_grid, 256>>>(s0, rowptr, ssrc, mean, mx, n);
    run_mixed(s0, mean, mx, 9, b_first + 2 * 3 * DD, g_firstP + 2 * 3 * DD,
              be_first + 2 * 3 * DD, w_first + 2 * 3, s1, 1);

    // ---- middle ops ----
    run_mixed(s0, mean, mx, 12, b_mid + 0 * 3 * DD, g_midP + 0 * 3 * DD,
              be_mid + 0 * 3 * DD, w_mid + 0 * 3, m0, 0);
    k_agg<<<agg_grid, 256>>>(s1, rowptr, ssrc, mean, mx, n);
    run_mixed(s1, mean, mx, 15, b_mid + 1 * 3 * DD, g_midP + 1 * 3 * DD,
              be_mid + 1 * 3 * DD, w_mid + 1 * 3, m1, 0);

    // ---- last ops ----
    k_agg<<<agg_grid, 256>>>(m0, rowptr, ssrc, mean, mx, n);
    run_mixed(m0, mean, mx, 18, b_last + 0 * 3 * DD, g_lastP + 0 * 3 * DD,
              be_last + 0 * 3 * DD, w_last + 0 * 3, sl, 0);
    k_agg<<<agg_grid, 256>>>(m1, rowptr, ssrc, mean, mx, n);
    run_mixed(m1, mean, mx, 21, b_last + 1 * 3 * DD, g_lastP + 1 * 3 * DD,
              be_last + 1 * 3 * DD, w_last + 1 * 3, sl, 1);

    // ---- final: cat GEMM (3 K-chunks) + column-norm ----
    cudaMemsetAsync(stats, 0, 2 * 3 * DD * sizeof(float));
    k_gemm_mma<<<dim3(gtiles, 1, 1), 256, SMEM_MMA>>>(
        m0, m1, sl, wpre + 24L * 32768, b_cat, yb, stats, n, ystride, 1);
    k_finalnorm<<<ew_grid, 256>>>(yb, stats, g_cat, be_cat, (float*)d_out, n);
}

// round 5
// speedup vs baseline: 1.2922x; 1.2922x over previous
#include <cuda_runtime.h>
#include <cuda_bf16.h>
#include <cstdint>
#include <math_constants.h>

#define NN 100000
#define EE 600000
#define DD 128
#define EPSLN 1e-5f
#define PADH 136   // smem row stride in halves (272B -> conflict-free ldmatrix)

// ---------------- scratch (device globals) -------------------------------------
__device__ float g_y[3L * NN * DD];
__device__ float g_hin[(size_t)NN * DD];
__device__ float g_s0[(size_t)NN * DD];
__device__ float g_s1[(size_t)NN * DD];
__device__ float g_m0[(size_t)NN * DD];
__device__ float g_m1[(size_t)NN * DD];
__device__ float g_slast[(size_t)NN * DD];
__device__ float g_mean[(size_t)NN * DD];
__device__ float g_max[(size_t)NN * DD];
__device__ float g_stats[2 * 3 * DD];
__device__ int   g_deg[NN];
__device__ int   g_rowptr[NN + 1];
__device__ int   g_cursor[NN];
__device__ int   g_ssrc[EE];
__device__ int   g_bsums[256];
__device__ __nv_bfloat16 g_wpre[27L * 32768];   // per matrix: hi[f*128+d] 16384, lo 16384

// ---------------- helpers ------------------------------------------------------
__device__ __forceinline__ uint32_t smem_u32(const void* p) {
    uint32_t a;
    asm("{ .reg .u64 t; cvta.to.shared.u64 t, %1; cvt.u32.u64 %0, t; }" : "=r"(a) : "l"(p));
    return a;
}
__device__ __forceinline__ uint32_t pk(__nv_bfloat16 a, __nv_bfloat16 b) {
    return (uint32_t)__bfloat16_as_ushort(a) | ((uint32_t)__bfloat16_as_ushort(b) << 16);
}
__device__ __forceinline__ void ldsm_x4(uint32_t& r0, uint32_t& r1, uint32_t& r2, uint32_t& r3,
                                        uint32_t addr) {
    asm volatile("ldmatrix.sync.aligned.m8n8.x4.shared.b16 {%0, %1, %2, %3}, [%4];"
                 : "=r"(r0), "=r"(r1), "=r"(r2), "=r"(r3) : "r"(addr));
}
__device__ __forceinline__ void mma16816(float* c, const uint32_t* a, const uint32_t* b) {
    asm volatile(
        "mma.sync.aligned.m16n8k16.row.col.f32.bf16.bf16.f32 "
        "{%0, %1, %2, %3}, {%4, %5, %6, %7}, {%8, %9}, {%0, %1, %2, %3};"
        : "+f"(c[0]), "+f"(c[1]), "+f"(c[2]), "+f"(c[3])
        : "r"(a[0]), "r"(a[1]), "r"(a[2]), "r"(a[3]), "r"(b[0]), "r"(b[1]));
}

// ---------------- weight prep: W[d][f] fp32 -> [f][k=d] bf16 hi/lo --------------
// grid = nmat * 8 blocks of 256 threads; each block does 2048 elements
__global__ void k_wprep(const float* __restrict__ W, __nv_bfloat16* __restrict__ out) {
    int m = blockIdx.x >> 3;
    int part = blockIdx.x & 7;
    const float* src = W + (size_t)m * 16384;
    __nv_bfloat16* ohi = out + (size_t)m * 32768;
    __nv_bfloat16* olo = ohi + 16384;
    int base = part * 2048;
    for (int i = threadIdx.x; i < 2048; i += blockDim.x) {
        int idx = base + i;
        int d = idx >> 7, f = idx & 127;
        float v = src[idx];
        __nv_bfloat16 h = __float2bfloat16(v);
        __nv_bfloat16 l = __float2bfloat16(v - __bfloat162float(h));
        ohi[f * 128 + d] = h;
        olo[f * 128 + d] = l;
    }
}

// ---------------- bf16-split tensor GEMM + fused column stats -------------------
// 512 threads, 16 warps 4x4, warp tile 32x32, accumulate 3 bf16 passes in fp32.
#define SMEM_MMA (4 * 128 * PADH * 2 + 1024)

__global__ __launch_bounds__(512, 1) void k_gemm_mma(
    const float* __restrict__ x0, const float* __restrict__ x1, const float* __restrict__ x2,
    const __nv_bfloat16* __restrict__ wpre, const float* __restrict__ bias,
    float* __restrict__ Y, float* __restrict__ stats, int n, size_t ystride, int catmode)
{
    extern __shared__ char sm[];
    __nv_bfloat16* Ahi = (__nv_bfloat16*)sm;
    __nv_bfloat16* Alo = Ahi + 128 * PADH;
    __nv_bfloat16* Bhi = Alo + 128 * PADH;
    __nv_bfloat16* Blo = Bhi + 128 * PADH;
    float* ssum = (float*)(Blo + 128 * PADH);
    float* ssq  = ssum + 128;

    int tid = threadIdx.x;
    int wid = tid >> 5, lane = tid & 31;
    int wm_ = wid >> 2, wn_ = wid & 3;     // 4x4 warp grid
    int kcand = catmode ? 0 : blockIdx.z;
    int nchunk = catmode ? 3 : 1;
    int row0 = blockIdx.x * 128;
    float* Yk = Y + (size_t)kcand * ystride;
    const float* bk = bias + kcand * DD;
    int so = kcand * DD;

    if (tid < 128) { ssum[tid] = 0.f; ssq[tid] = 0.f; }

    float c[2][4][4];
    #pragma unroll
    for (int i = 0; i < 2; i++)
        #pragma unroll
        for (int j = 0; j < 4; j++)
            #pragma unroll
            for (int q = 0; q < 4; q++) c[i][j][q] = 0.f;

    // ldmatrix lane mappings
    int a_row = wm_ * 32 + (lane & 15);
    int a_k8 = (lane >> 4) * 8;
    int b_f = wn_ * 32 + ((lane >> 4) << 3) + (lane & 7);
    int b_k8 = ((lane >> 3) & 1) * 8;
    uint32_t uAhi = smem_u32(Ahi), uAlo = smem_u32(Alo);
    uint32_t uBhi = smem_u32(Bhi), uBlo = smem_u32(Blo);

    for (int ch = 0; ch < nchunk; ch++) {
        const float* X = catmode ? (ch == 0 ? x0 : (ch == 1 ? x1 : x2))
                                 : (kcand == 0 ? x0 : (kcand == 1 ? x1 : x2));
        const __nv_bfloat16* wm = wpre + (size_t)(catmode ? ch : kcand) * 32768;

        if (ch > 0) __syncthreads();

        // B copy (pre-transposed rows) -> padded smem
        for (int i = tid; i < 2048; i += 512) {
            int f = i >> 4, seg = i & 15;
            uint4 h = ((const uint4*)wm)[i];
            uint4 l = ((const uint4*)(wm + 16384))[i];
            *(uint4*)(Bhi + f * PADH + seg * 8) = h;
            *(uint4*)(Blo + f * PADH + seg * 8) = l;
        }
        // A convert fp32 -> bf16 hi/lo : each thread does one row-quarter (32 cols)
        {
            int row = tid >> 2, sg = tid & 3;
            int gr = row0 + row;
            __nv_bfloat16* dh = Ahi + row * PADH + sg * 32;
            __nv_bfloat16* dl = Alo + row * PADH + sg * 32;
            #pragma unroll
            for (int q = 0; q < 8; q++) {
                float4 v = (gr < n) ? *(const float4*)(X + (size_t)gr * DD + sg * 32 + q * 4)
                                    : make_float4(0.f, 0.f, 0.f, 0.f);
                __nv_bfloat16 h0 = __float2bfloat16(v.x), h1 = __float2bfloat16(v.y);
                __nv_bfloat16 h2 = __float2bfloat16(v.z), h3 = __float2bfloat16(v.w);
                __nv_bfloat16 l0 = __float2bfloat16(v.x - __bfloat162float(h0));
                __nv_bfloat16 l1 = __float2bfloat16(v.y - __bfloat162float(h1));
                __nv_bfloat16 l2 = __float2bfloat16(v.z - __bfloat162float(h2));
                __nv_bfloat16 l3 = __float2bfloat16(v.w - __bfloat162float(h3));
                *(uint2*)(dh + q * 4) = make_uint2(pk(h0, h1), pk(h2, h3));
                *(uint2*)(dl + q * 4) = make_uint2(pk(l0, l1), pk(l2, l3));
            }
        }
        __syncthreads();

        // 3 bf16 passes: hi*hi, hi*lo, lo*hi
        #pragma unroll
        for (int seg = 0; seg < 3; seg++) {
            uint32_t Ab = (seg < 2) ? uAhi : uAlo;
            uint32_t Bb = (seg == 1) ? uBlo : uBhi;
            #pragma unroll
            for (int k = 0; k < 8; k++) {
                uint32_t a[2][4];
                #pragma unroll
                for (int mt = 0; mt < 2; mt++) {
                    uint32_t addr = Ab + (uint32_t)(((a_row + mt * 16) * PADH + k * 16 + a_k8) * 2);
                    ldsm_x4(a[mt][0], a[mt][1], a[mt][2], a[mt][3], addr);
                }
                uint32_t b[2][4];
                #pragma unroll
                for (int p = 0; p < 2; p++) {
                    uint32_t addr = Bb + (uint32_t)(((b_f + p * 16) * PADH + k * 16 + b_k8) * 2);
                    ldsm_x4(b[p][0], b[p][1], b[p][2], b[p][3], addr);
                }
                #pragma unroll
                for (int mt = 0; mt < 2; mt++)
                    #pragma unroll
                    for (int nt = 0; nt < 4; nt++)
                        mma16816(c[mt][nt], a[mt], &b[nt >> 1][(nt & 1) * 2]);
            }
        }
    }

    // ---------------- epilogue: bias, store Y, fused column stats ---------------
    int erow = lane >> 2, ecp = lane & 3;
    float2 bb[4];
    #pragma unroll
    for (int nt = 0; nt < 4; nt++)
        bb[nt] = *(const float2*)(bk + wn_ * 32 + nt * 8 + ecp * 2);

    float lsum[8], lsq[8];
    #pragma unroll
    for (int j = 0; j < 8; j++) { lsum[j] = 0.f; lsq[j] = 0.f; }

    #pragma unroll
    for (int mt = 0; mt < 2; mt++) {
        int r0g = row0 + wm_ * 32 + mt * 16 + erow;
        int r1g = r0g + 8;
        #pragma unroll
        for (int nt = 0; nt < 4; nt++) {
            int cbase = wn_ * 32 + nt * 8 + ecp * 2;
            float v00 = c[mt][nt][0] + bb[nt].x;
            float v01 = c[mt][nt][1] + bb[nt].y;
            float v10 = c[mt][nt][2] + bb[nt].x;
            float v11 = c[mt][nt][3] + bb[nt].y;
            if (r0g < n) {
                *(float2*)(Yk + (size_t)r0g * DD + cbase) = make_float2(v00, v01);
                lsum[nt * 2]     += v00; lsq[nt * 2]     += v00 * v00;
                lsum[nt * 2 + 1] += v01; lsq[nt * 2 + 1] += v01 * v01;
            }
            if (r1g < n) {
                *(float2*)(Yk + (size_t)r1g * DD + cbase) = make_float2(v10, v11);
                lsum[nt * 2]     += v10; lsq[nt * 2]     += v10 * v10;
                lsum[nt * 2 + 1] += v11; lsq[nt * 2 + 1] += v11 * v11;
            }
        }
    }
    #pragma unroll
    for (int nt = 0; nt < 4; nt++) {
        int cbase = wn_ * 32 + nt * 8 + ecp * 2;
        atomicAdd(&ssum[cbase],     lsum[nt * 2]);
        atomicAdd(&ssq[cbase],      lsq[nt * 2]);
        atomicAdd(&ssum[cbase + 1], lsum[nt * 2 + 1]);
        atomicAdd(&ssq[cbase + 1],  lsq[nt * 2 + 1]);
    }
    __syncthreads();
    if (tid < 128) {
        atomicAdd(&stats[so + tid], ssum[tid]);
        atomicAdd(&stats[3 * DD + so + tid], ssq[tid]);
    }
}

// ---------------- CSR build ---------------------------------------------------
__global__ void k_hist(const int* __restrict__ dst, int* deg, int e) {
    int i = blockIdx.x * blockDim.x + threadIdx.x;
    if (i < e) atomicAdd(&deg[dst[i]], 1);
}
__global__ void k_scan_block(const int* __restrict__ deg, int* incl, int* bsums, int n) {
    __shared__ int sh[1024];
    int i = blockIdx.x * 1024 + threadIdx.x;
    int v = (i < n) ? deg[i] : 0;
    sh[threadIdx.x] = v;
    __syncthreads();
    for (int off = 1; off < 1024; off <<= 1) {
        int t = (threadIdx.x >= off) ? sh[threadIdx.x - off] : 0;
        __syncthreads();
        sh[threadIdx.x] += t;
        __syncthreads();
    }
    if (i < n) incl[i] = sh[threadIdx.x];
    if (threadIdx.x == 1023) bsums[blockIdx.x] = sh[1023];
}
__global__ void k_scan_sums(int* bsums, int nb) {
    if (threadIdx.x == 0 && blockIdx.x == 0) {
        int run = 0;
        for (int i = 0; i < nb; i++) { int t = bsums[i]; bsums[i] = run; run += t; }
    }
}
__global__ void k_scan_fin(const int* __restrict__ deg, const int* __restrict__ incl,
                           const int* __restrict__ bsums, int* rowptr, int* cursor, int n, int e) {
    int i = blockIdx.x * blockDim.x + threadIdx.x;
    if (i < n) {
        int ex = incl[i] - deg[i] + bsums[i >> 10];
        rowptr[i] = ex;
        cursor[i] = ex;
        if (i == n - 1) rowptr[n] = e;
    }
}
__global__ void k_scatter(const int* __restrict__ src, const int* __restrict__ dst,
                          int* cursor, int* ssrc, int e) {
    int i = blockIdx.x * blockDim.x + threadIdx.x;
    if (i < e) {
        int p = atomicAdd(&cursor[dst[i]], 1);
        ssrc[p] = src[i];
    }
}

// ---------------- graph aggregation (mean + max), warp per node ---------------
__global__ void k_agg(const float* __restrict__ h, const int* __restrict__ rowptr,
                      const int* __restrict__ ssrc, float* __restrict__ meanout,
                      float* __restrict__ maxout, int n) {
    int warp = (blockIdx.x * blockDim.x + threadIdx.x) >> 5;
    int lane = threadIdx.x & 31;
    if (warp >= n) return;
    int beg = rowptr[warp], end = rowptr[warp + 1];
    float4 s  = make_float4(0.f, 0.f, 0.f, 0.f);
    float4 mx = make_float4(-CUDART_INF_F, -CUDART_INF_F, -CUDART_INF_F, -CUDART_INF_F);
    for (int i = beg; i < end; i++) {
        int src = ssrc[i];
        float4 v = ((const float4*)(h + (size_t)src * DD))[lane];
        s.x += v.x; s.y += v.y; s.z += v.z; s.w += v.w;
        mx.x = fmaxf(mx.x, v.x); mx.y = fmaxf(mx.y, v.y);
        mx.z = fmaxf(mx.z, v.z); mx.w = fmaxf(mx.w, v.w);
    }
    int deg = end - beg;
    float inv = 1.0f / (float)max(deg, 1);
    float4 mo = make_float4(s.x * inv, s.y * inv, s.z * inv, s.w * inv);
    float4 xo = (deg > 0) ? mx : make_float4(0.f, 0.f, 0.f, 0.f);
    ((float4*)(meanout + (size_t)warp * DD))[lane] = mo;
    ((float4*)(maxout  + (size_t)warp * DD))[lane] = xo;
}

// ---------------- elementwise pre-candidates ----------------------------------
__global__ void k_pre(const float* __restrict__ a, const float* __restrict__ b,
                      float* __restrict__ p1, float* __restrict__ p2, int total) {
    int i = blockIdx.x * blockDim.x + threadIdx.x;
    if (i < total) {
        float x = a[i], y = b[i];
        p1[i] = x - y;
        p2[i] = x * y;
    }
}

// ---------------- mixed epilogue: normalize + relu + weighted k-sum -----------
__global__ void k_combine(const float* __restrict__ y, const float* __restrict__ stats,
                          const float* __restrict__ wrow, const float* __restrict__ gg,
                          const float* __restrict__ be, float* __restrict__ out,
                          int n, int accum) {
    int idx = blockIdx.x * blockDim.x + threadIdx.x;
    int total = n * DD;
    if (idx >= total) return;
    int d = idx & (DD - 1);
    float fn = (float)n;
    float acc = 0.f;
    #pragma unroll
    for (int k = 0; k < 3; k++) {
        float mu  = stats[k * DD + d] / fn;
        float var = stats[3 * DD + k * DD + d] / fn - mu * mu;
        float rs  = rsqrtf(var + EPSLN);
        float v = y[(size_t)k * n * DD + idx];
        float t = (v - mu) * rs * gg[k * DD + d] + be[k * DD + d];
        t = fmaxf(t, 0.f);
        acc += wrow[k] * t;
    }
    out[idx] = accum ? (out[idx] + acc) : acc;
}

// ---------------- final column-norm + relu ------------------------------------
__global__ void k_finalnorm(const float* __restrict__ h, const float* __restrict__ stats,
                            const float* __restrict__ gc, const float* __restrict__ bec,
                            float* __restrict__ out, int n) {
    int idx = blockIdx.x * blockDim.x + threadIdx.x;
    int total = n * DD;
    if (idx >= total) return;
    int d = idx & (DD - 1);
    float fn = (float)n;
    float mu  = stats[d] / fn;
    float var = stats[3 * DD + d] / fn - mu * mu;
    float rs  = rsqrtf(var + EPSLN);
    float v = (h[idx] - mu) * rs * gc[d] + bec[d];
    out[idx] = fmaxf(v, 0.f);
}

// ---------------- host orchestration ------------------------------------------
extern "C" void kernel_launch(void* const* d_in, const int* in_sizes, int n_in,
                              void* d_out, int out_size) {
    const float* src_emb = (const float*)d_in[0];
    const float* hr      = (const float*)d_in[1];
    const int*   esrc    = (const int*)d_in[2];
    const int*   edst    = (const int*)d_in[3];
    const float* w_zero  = (const float*)d_in[4];
    const float* w_first = (const float*)d_in[5];
    const float* w_mid   = (const float*)d_in[6];
    const float* w_last  = (const float*)d_in[7];
    const float* W_zero  = (const float*)d_in[8];
    const float* b_zero  = (const float*)d_in[9];
    const float* g_zeroP = (const float*)d_in[10];
    const float* be_zero = (const float*)d_in[11];
    const float* W_first = (const float*)d_in[12];
    const float* b_first = (const float*)d_in[13];
    const float* g_firstP= (const float*)d_in[14];
    const float* be_first= (const float*)d_in[15];
    const float* W_mid   = (const float*)d_in[16];
    const float* b_mid   = (const float*)d_in[17];
    const float* g_midP  = (const float*)d_in[18];
    const float* be_mid  = (const float*)d_in[19];
    const float* W_last  = (const float*)d_in[20];
    const float* b_last  = (const float*)d_in[21];
    const float* g_lastP = (const float*)d_in[22];
    const float* be_last = (const float*)d_in[23];
    const float* W_cat   = (const float*)d_in[24];
    const float* b_cat   = (const float*)d_in[25];
    const float* g_cat   = (const float*)d_in[26];
    const float* be_cat  = (const float*)d_in[27];

    int n = in_sizes[0] / DD;
    int e = in_sizes[2];

    float *yb, *hin, *s0, *s1, *m0, *m1, *sl, *mean, *mx, *stats;
    int *deg, *rowptr, *cursor, *ssrc, *bsums;
    __nv_bfloat16* wpre;
    cudaGetSymbolAddress((void**)&yb, g_y);
    cudaGetSymbolAddress((void**)&hin, g_hin);
    cudaGetSymbolAddress((void**)&s0, g_s0);
    cudaGetSymbolAddress((void**)&s1, g_s1);
    cudaGetSymbolAddress((void**)&m0, g_m0);
    cudaGetSymbolAddress((void**)&m1, g_m1);
    cudaGetSymbolAddress((void**)&sl, g_slast);
    cudaGetSymbolAddress((void**)&mean, g_mean);
    cudaGetSymbolAddress((void**)&mx, g_max);
    cudaGetSymbolAddress((void**)&stats, g_stats);
    cudaGetSymbolAddress((void**)&deg, g_deg);
    cudaGetSymbolAddress((void**)&rowptr, g_rowptr);
    cudaGetSymbolAddress((void**)&cursor, g_cursor);
    cudaGetSymbolAddress((void**)&ssrc, g_ssrc);
    cudaGetSymbolAddress((void**)&bsums, g_bsums);
    cudaGetSymbolAddress((void**)&wpre, g_wpre);

    cudaFuncSetAttribute(k_gemm_mma, cudaFuncAttributeMaxDynamicSharedMemorySize, SMEM_MMA);

    int total = n * DD;
    size_t ystride = (size_t)n * DD;
    int gtiles = (n + 127) / 128;
    int ew_grid = (total + 255) / 256;
    int agg_grid = (n + 7) / 8;
    int eb = (e + 255) / 256;
    int nb1024 = (n + 1023) / 1024;

    // ---- weight prep (8 blocks per matrix) ----
    k_wprep<<<3 * 8, 256>>>(W_zero,  wpre + 0L  * 32768);
    k_wprep<<<9 * 8, 256>>>(W_first, wpre + 3L  * 32768);
    k_wprep<<<6 * 8, 256>>>(W_mid,   wpre + 12L * 32768);
    k_wprep<<<6 * 8, 256>>>(W_last,  wpre + 18L * 32768);
    k_wprep<<<3 * 8, 256>>>(W_cat,   wpre + 24L * 32768);

    // ---- CSR build ----
    cudaMemsetAsync(deg, 0, (size_t)n * sizeof(int));
    k_hist<<<eb, 256>>>(edst, deg, e);
    k_scan_block<<<nb1024, 1024>>>(deg, cursor, bsums, n);
    k_scan_sums<<<1, 32>>>(bsums, nb1024);
    k_scan_fin<<<(n + 255) / 256, 256>>>(deg, cursor, bsums, rowptr, cursor, n, e);
    k_scatter<<<eb, 256>>>(esrc, edst, cursor, ssrc, e);

    auto run_mixed = [&](const float* x0, const float* x1, const float* x2,
                         int opmat, const float* B, const float* G, const float* BE,
                         const float* wrow, float* out, int accum) {
        cudaMemsetAsync(stats, 0, 2 * 3 * DD * sizeof(float));
        k_gemm_mma<<<dim3(gtiles, 1, 3), 512, SMEM_MMA>>>(
            x0, x1, x2, wpre + (size_t)opmat * 32768, B, yb, stats, n, ystride, 0);
        k_combine<<<ew_grid, 256>>>(yb, stats, wrow, G, BE, out, n, accum);
    };

    // ---- zero op ----
    k_pre<<<ew_grid, 256>>>(src_emb, hr, mean, mx, total);
    run_mixed(src_emb, mean, mx, 0, b_zero, g_zeroP, be_zero, w_zero, hin, 0);

    // ---- first ops ----
    k_agg<<<agg_grid, 256>>>(hin, rowptr, ssrc, mean, mx, n);
    run_mixed(hin, mean, mx, 3, b_first + 0 * 3 * DD, g_firstP + 0 * 3 * DD,
              be_first + 0 * 3 * DD, w_first + 0 * 3, s0, 0);
    run_mixed(hin, mean, mx, 6, b_first + 1 * 3 * DD, g_firstP + 1 * 3 * DD,
              be_first + 1 * 3 * DD, w_first + 1 * 3, s1, 0);
    k_agg<<<agg_grid, 256>>>(s0, rowptr, ssrc, mean, mx, n);
    run_mixed(s0, mean, mx, 9, b_first + 2 * 3 * DD, g_firstP + 2 * 3 * DD,
              be_first + 2 * 3 * DD, w_first + 2 * 3, s1, 1);

    // ---- middle ops ----
    run_mixed(s0, mean, mx, 12, b_mid + 0 * 3 * DD, g_midP + 0 * 3 * DD,
              be_mid + 0 * 3 * DD, w_mid + 0 * 3, m0, 0);
    k_agg<<<agg_grid, 256>>>(s1, rowptr, ssrc, mean, mx, n);
    run_mixed(s1, mean, mx, 15, b_mid + 1 * 3 * DD, g_midP + 1 * 3 * DD,
              be_mid + 1 * 3 * DD, w_mid + 1 * 3, m1, 0);

    // ---- last ops ----
    k_agg<<<agg_grid, 256>>>(m0, rowptr, ssrc, mean, mx, n);
    run_mixed(m0, mean, mx, 18, b_last + 0 * 3 * DD, g_lastP + 0 * 3 * DD,
              be_last + 0 * 3 * DD, w_last + 0 * 3, sl, 0);
    k_agg<<<agg_grid, 256>>>(m1, rowptr, ssrc, mean, mx, n);
    run_mixed(m1, mean, mx, 21, b_last + 1 * 3 * DD, g_lastP + 1 * 3 * DD,
              be_last + 1 * 3 * DD, w_last + 1 * 3, sl, 1);

    // ---- final: cat GEMM (3 K-chunks) + column-norm ----
    cudaMemsetAsync(stats, 0, 2 * 3 * DD * sizeof(float));
    k_gemm_mma<<<dim3(gtiles, 1, 1), 512, SMEM_MMA>>>(
        m0, m1, sl, wpre + 24L * 32768, b_cat, yb, stats, n, ystride, 1);
    k_finalnorm<<<ew_grid, 256>>>(yb, stats, g_cat, be_cat, (float*)d_out, n);
}

// round 6
// speedup vs baseline: 1.3434x; 1.0397x over previous
#include <cuda_runtime.h>
#include <cuda_bf16.h>
#include <cstdint>
#include <math_constants.h>

#define NN 100000
#define EE 600000
#define DD 128
#define EPSLN 1e-5f
#define PADK 72    // smem row stride in halves for 64-col tiles (144B, conflict-free ldmatrix)

// ---------------- scratch (device globals) -------------------------------------
__device__ float g_y[3L * NN * DD];
__device__ float g_hin[(size_t)NN * DD];
__device__ float g_s0[(size_t)NN * DD];
__device__ float g_s1[(size_t)NN * DD];
__device__ float g_m0[(size_t)NN * DD];
__device__ float g_m1[(size_t)NN * DD];
__device__ float g_slast[(size_t)NN * DD];
__device__ float g_mean[(size_t)NN * DD];
__device__ float g_max[(size_t)NN * DD];
__device__ float g_statsA[9 * 2 * 3 * DD];   // 9 op slots x (sum, sumsq) x 3 x 128
__device__ int   g_deg[NN];
__device__ int   g_rowptr[NN + 1];
__device__ int   g_cursor[NN];
__device__ int   g_ssrc[EE];
__device__ int   g_bsums[256];
__device__ __nv_bfloat16 g_wpre[27L * 32768];   // per matrix: hi[f*128+d] 16384, lo 16384

// ---------------- helpers ------------------------------------------------------
__device__ __forceinline__ uint32_t smem_u32(const void* p) {
    uint32_t a;
    asm("{ .reg .u64 t; cvta.to.shared.u64 t, %1; cvt.u32.u64 %0, t; }" : "=r"(a) : "l"(p));
    return a;
}
__device__ __forceinline__ uint32_t pk(__nv_bfloat16 a, __nv_bfloat16 b) {
    return (uint32_t)__bfloat16_as_ushort(a) | ((uint32_t)__bfloat16_as_ushort(b) << 16);
}
__device__ __forceinline__ void ldsm_x4(uint32_t& r0, uint32_t& r1, uint32_t& r2, uint32_t& r3,
                                        uint32_t addr) {
    asm volatile("ldmatrix.sync.aligned.m8n8.x4.shared.b16 {%0, %1, %2, %3}, [%4];"
                 : "=r"(r0), "=r"(r1), "=r"(r2), "=r"(r3) : "r"(addr));
}
__device__ __forceinline__ void mma16816(float* c, const uint32_t* a, const uint32_t* b) {
    asm volatile(
        "mma.sync.aligned.m16n8k16.row.col.f32.bf16.bf16.f32 "
        "{%0, %1, %2, %3}, {%4, %5, %6, %7}, {%8, %9}, {%0, %1, %2, %3};"
        : "+f"(c[0]), "+f"(c[1]), "+f"(c[2]), "+f"(c[3])
        : "r"(a[0]), "r"(a[1]), "r"(a[2]), "r"(a[3]), "r"(b[0]), "r"(b[1]));
}
__device__ __forceinline__ void cpasync16(uint32_t saddr, const void* gaddr) {
    asm volatile("cp.async.cg.shared.global [%0], [%1], 16;" :: "r"(saddr), "l"(gaddr));
}
__device__ __forceinline__ void cpasync_waitall() {
    asm volatile("cp.async.commit_group;");
    asm volatile("cp.async.wait_group 0;");
}

// ---------------- weight prep: W[d][f] fp32 -> [f][k=d] bf16 hi/lo --------------
__global__ void k_wprep(const float* __restrict__ W, __nv_bfloat16* __restrict__ out,
                        float* statszero, int zn) {
    if (statszero && blockIdx.x == 0) {
        for (int i = threadIdx.x; i < zn; i += blockDim.x) statszero[i] = 0.f;
    }
    int m = blockIdx.x >> 3;
    int part = blockIdx.x & 7;
    const float* src = W + (size_t)m * 16384;
    __nv_bfloat16* ohi = out + (size_t)m * 32768;
    __nv_bfloat16* olo = ohi + 16384;
    int base = part * 2048;
    for (int i = threadIdx.x; i < 2048; i += blockDim.x) {
        int idx = base + i;
        int d = idx >> 7, f = idx & 127;
        float v = src[idx];
        __nv_bfloat16 h = __float2bfloat16(v);
        __nv_bfloat16 l = __float2bfloat16(v - __bfloat162float(h));
        ohi[f * 128 + d] = h;
        olo[f * 128 + d] = l;
    }
}

// ---------------- bf16-split tensor GEMM + fused column stats -------------------
// 256 threads, 8 warps 4x2, warp tile 32x64; K in two 64-chunks; 2 CTAs/SM.
#define TILE_HALVES (128 * PADK)             // 9216 halves = 18432 B
#define SMEM_MMA (4 * TILE_HALVES * 2 + 1024)

__global__ __launch_bounds__(256, 2) void k_gemm_mma(
    const float* __restrict__ x0, const float* __restrict__ x1, const float* __restrict__ x2,
    const __nv_bfloat16* __restrict__ wpre, const float* __restrict__ bias,
    float* __restrict__ Y, float* __restrict__ stats, int n, size_t ystride,
    int catmode, int premode)
{
    extern __shared__ char sm[];
    __nv_bfloat16* Ahi = (__nv_bfloat16*)sm;
    __nv_bfloat16* Alo = Ahi + TILE_HALVES;
    __nv_bfloat16* Bhi = Alo + TILE_HALVES;
    __nv_bfloat16* Blo = Bhi + TILE_HALVES;
    float* ssum = (float*)(Blo + TILE_HALVES);
    float* ssq  = ssum + 128;

    int tid = threadIdx.x;
    int wid = tid >> 5, lane = tid & 31;
    int wm_ = wid >> 1, wn_ = wid & 1;     // 4x2 warp grid, 32x64 warp tile
    int kcand = catmode ? 0 : blockIdx.z;
    int nchunk = catmode ? 3 : 1;
    int row0 = blockIdx.x * 128;
    float* Yk = Y + (size_t)kcand * ystride;
    const float* bk = bias + kcand * DD;
    int so = kcand * DD;

    if (tid < 128) { ssum[tid] = 0.f; ssq[tid] = 0.f; }

    float c[2][8][4];
    #pragma unroll
    for (int i = 0; i < 2; i++)
        #pragma unroll
        for (int j = 0; j < 8; j++)
            #pragma unroll
            for (int q = 0; q < 4; q++) c[i][j][q] = 0.f;

    int a_row = wm_ * 32 + (lane & 15);
    int a_k8 = (lane >> 4) * 8;
    int b_f = wn_ * 64 + ((lane >> 4) << 3) + (lane & 7);
    int b_k8 = ((lane >> 3) & 1) * 8;
    uint32_t uAhi = smem_u32(Ahi), uAlo = smem_u32(Alo);
    uint32_t uBhi = smem_u32(Bhi), uBlo = smem_u32(Blo);

    for (int c3 = 0; c3 < nchunk; c3++) {
        const float* X = catmode ? (c3 == 0 ? x0 : (c3 == 1 ? x1 : x2)) : x0;
        const __nv_bfloat16* wm = wpre + (size_t)(catmode ? c3 : kcand) * 32768;

        for (int ch = 0; ch < 2; ch++) {          // K chunks of 64
            if (c3 + ch > 0) __syncthreads();     // prior mma reads done before refill

            // B fill via cp.async: rows f 0..127, cols ch*64..+64
            {
                int f = tid >> 1, half2 = (tid & 1) * 4;  // 2 threads/row, 4 uint4 each
                uint32_t dsth = uBhi + (uint32_t)((f * PADK) * 2) + (uint32_t)((half2) * 16);
                uint32_t dstl = uBlo + (uint32_t)((f * PADK) * 2) + (uint32_t)((half2) * 16);
                const char* sh = (const char*)(wpre) + ((size_t)(catmode ? c3 : kcand) * 32768
                                 + (size_t)f * 128 + ch * 64) * 2 + half2 * 16;
                const char* sl = sh + 16384 * 2;
                #pragma unroll
                for (int q = 0; q < 4; q++) {
                    cpasync16(dsth + q * 16, sh + q * 16);
                    cpasync16(dstl + q * 16, sl + q * 16);
                }
            }
            // A convert fp32 -> bf16 hi/lo (cols ch*64..+64); optional fused pre-op
            {
                int row = tid >> 1, sg = tid & 1;
                int gr = row0 + row;
                __nv_bfloat16* dh = Ahi + row * PADK + sg * 32;
                __nv_bfloat16* dl = Alo + row * PADK + sg * 32;
                int cbase = ch * 64 + sg * 32;
                #pragma unroll
                for (int q = 0; q < 8; q++) {
                    float4 v = make_float4(0.f, 0.f, 0.f, 0.f);
                    if (gr < n) {
                        v = *(const float4*)(x0 + (size_t)gr * DD + cbase + q * 4);
                        if (premode && kcand > 0) {
                            float4 b = *(const float4*)(x1 + (size_t)gr * DD + cbase + q * 4);
                            if (kcand == 1) { v.x -= b.x; v.y -= b.y; v.z -= b.z; v.w -= b.w; }
                            else            { v.x *= b.x; v.y *= b.y; v.z *= b.z; v.w *= b.w; }
                        } else if (!premode && !catmode) {
                            if (kcand == 1) v = *(const float4*)(x1 + (size_t)gr * DD + cbase + q * 4);
                            else if (kcand == 2) v = *(const float4*)(x2 + (size_t)gr * DD + cbase + q * 4);
                        } else if (catmode) {
                            v = *(const float4*)(X + (size_t)gr * DD + cbase + q * 4);
                        }
                    }
                    __nv_bfloat16 h0 = __float2bfloat16(v.x), h1 = __float2bfloat16(v.y);
                    __nv_bfloat16 h2 = __float2bfloat16(v.z), h3 = __float2bfloat16(v.w);
                    __nv_bfloat16 l0 = __float2bfloat16(v.x - __bfloat162float(h0));
                    __nv_bfloat16 l1 = __float2bfloat16(v.y - __bfloat162float(h1));
                    __nv_bfloat16 l2 = __float2bfloat16(v.z - __bfloat162float(h2));
                    __nv_bfloat16 l3 = __float2bfloat16(v.w - __bfloat162float(h3));
                    *(uint2*)(dh + q * 4) = make_uint2(pk(h0, h1), pk(h2, h3));
                    *(uint2*)(dl + q * 4) = make_uint2(pk(l0, l1), pk(l2, l3));
                }
            }
            cpasync_waitall();
            __syncthreads();

            // 3 bf16 passes: hi*hi, hi*lo, lo*hi ; 4 k-steps per 64-chunk
            #pragma unroll
            for (int seg = 0; seg < 3; seg++) {
                uint32_t Ab = (seg < 2) ? uAhi : uAlo;
                uint32_t Bb = (seg == 1) ? uBlo : uBhi;
                #pragma unroll
                for (int k = 0; k < 4; k++) {
                    uint32_t a[2][4];
                    #pragma unroll
                    for (int mt = 0; mt < 2; mt++) {
                        uint32_t addr = Ab + (uint32_t)(((a_row + mt * 16) * PADK + k * 16 + a_k8) * 2);
                        ldsm_x4(a[mt][0], a[mt][1], a[mt][2], a[mt][3], addr);
                    }
                    uint32_t b[4][4];
                    #pragma unroll
                    for (int p = 0; p < 4; p++) {
                        uint32_t addr = Bb + (uint32_t)(((b_f + p * 16) * PADK + k * 16 + b_k8) * 2);
                        ldsm_x4(b[p][0], b[p][1], b[p][2], b[p][3], addr);
                    }
                    #pragma unroll
                    for (int mt = 0; mt < 2; mt++)
                        #pragma unroll
                        for (int nt = 0; nt < 8; nt++)
                            mma16816(c[mt][nt], a[mt], &b[nt >> 1][(nt & 1) * 2]);
                }
            }
        }
    }

    // ---------------- epilogue: bias, store Y, fused column stats ---------------
    int erow = lane >> 2, ecp = lane & 3;
    float2 bb[8];
    #pragma unroll
    for (int nt = 0; nt < 8; nt++)
        bb[nt] = *(const float2*)(bk + wn_ * 64 + nt * 8 + ecp * 2);

    float lsum[16], lsq[16];
    #pragma unroll
    for (int j = 0; j < 16; j++) { lsum[j] = 0.f; lsq[j] = 0.f; }

    #pragma unroll
    for (int mt = 0; mt < 2; mt++) {
        int r0g = row0 + wm_ * 32 + mt * 16 + erow;
        int r1g = r0g + 8;
        #pragma unroll
        for (int nt = 0; nt < 8; nt++) {
            int cbase = wn_ * 64 + nt * 8 + ecp * 2;
            float v00 = c[mt][nt][0] + bb[nt].x;
            float v01 = c[mt][nt][1] + bb[nt].y;
            float v10 = c[mt][nt][2] + bb[nt].x;
            float v11 = c[mt][nt][3] + bb[nt].y;
            if (r0g < n) {
                *(float2*)(Yk + (size_t)r0g * DD + cbase) = make_float2(v00, v01);
                lsum[nt * 2]     += v00; lsq[nt * 2]     += v00 * v00;
                lsum[nt * 2 + 1] += v01; lsq[nt * 2 + 1] += v01 * v01;
            }
            if (r1g < n) {
                *(float2*)(Yk + (size_t)r1g * DD + cbase) = make_float2(v10, v11);
                lsum[nt * 2]     += v10; lsq[nt * 2]     += v10 * v10;
                lsum[nt * 2 + 1] += v11; lsq[nt * 2 + 1] += v11 * v11;
            }
        }
    }
    #pragma unroll
    for (int nt = 0; nt < 8; nt++) {
        int cbase = wn_ * 64 + nt * 8 + ecp * 2;
        atomicAdd(&ssum[cbase],     lsum[nt * 2]);
        atomicAdd(&ssq[cbase],      lsq[nt * 2]);
        atomicAdd(&ssum[cbase + 1], lsum[nt * 2 + 1]);
        atomicAdd(&ssq[cbase + 1],  lsq[nt * 2 + 1]);
    }
    __syncthreads();
    if (tid < 128) {
        atomicAdd(&stats[so + tid], ssum[tid]);
        atomicAdd(&stats[3 * DD + so + tid], ssq[tid]);
    }
}

// ---------------- CSR build ---------------------------------------------------
__global__ void k_hist(const int* __restrict__ dst, int* deg, int e) {
    int i = blockIdx.x * blockDim.x + threadIdx.x;
    if (i < e) atomicAdd(&deg[dst[i]], 1);
}
__global__ void k_scan_block(const int* __restrict__ deg, int* incl, int* bsums, int n) {
    __shared__ int sh[1024];
    int i = blockIdx.x * 1024 + threadIdx.x;
    int v = (i < n) ? deg[i] : 0;
    sh[threadIdx.x] = v;
    __syncthreads();
    for (int off = 1; off < 1024; off <<= 1) {
        int t = (threadIdx.x >= off) ? sh[threadIdx.x - off] : 0;
        __syncthreads();
        sh[threadIdx.x] += t;
        __syncthreads();
    }
    if (i < n) incl[i] = sh[threadIdx.x];
    if (threadIdx.x == 1023) bsums[blockIdx.x] = sh[1023];
}
__global__ void k_scan_sums(int* bsums, int nb) {
    if (threadIdx.x == 0 && blockIdx.x == 0) {
        int run = 0;
        for (int i = 0; i < nb; i++) { int t = bsums[i]; bsums[i] = run; run += t; }
    }
}
__global__ void k_scan_fin(const int* __restrict__ deg, const int* __restrict__ incl,
                           const int* __restrict__ bsums, int* rowptr, int* cursor, int n, int e) {
    int i = blockIdx.x * blockDim.x + threadIdx.x;
    if (i < n) {
        int ex = incl[i] - deg[i] + bsums[i >> 10];
        rowptr[i] = ex;
        cursor[i] = ex;
        if (i == n - 1) rowptr[n] = e;
    }
}
__global__ void k_scatter(const int* __restrict__ src, const int* __restrict__ dst,
                          int* cursor, int* ssrc, int e) {
    int i = blockIdx.x * blockDim.x + threadIdx.x;
    if (i < e) {
        int p = atomicAdd(&cursor[dst[i]], 1);
        ssrc[p] = src[i];
    }
}

// ---------------- graph aggregation (mean + max), warp per node ---------------
__global__ void k_agg(const float* __restrict__ h, const int* __restrict__ rowptr,
                      const int* __restrict__ ssrc, float* __restrict__ meanout,
                      float* __restrict__ maxout, int n) {
    int warp = (blockIdx.x * blockDim.x + threadIdx.x) >> 5;
    int lane = threadIdx.x & 31;
    if (warp >= n) return;
    int beg = rowptr[warp], end = rowptr[warp + 1];
    float4 s  = make_float4(0.f, 0.f, 0.f, 0.f);
    float4 mx = make_float4(-CUDART_INF_F, -CUDART_INF_F, -CUDART_INF_F, -CUDART_INF_F);
    for (int i = beg; i < end; i++) {
        int src = ssrc[i];
        float4 v = ((const float4*)(h + (size_t)src * DD))[lane];
        s.x += v.x; s.y += v.y; s.z += v.z; s.w += v.w;
        mx.x = fmaxf(mx.x, v.x); mx.y = fmaxf(mx.y, v.y);
        mx.z = fmaxf(mx.z, v.z); mx.w = fmaxf(mx.w, v.w);
    }
    int deg = end - beg;
    float inv = 1.0f / (float)max(deg, 1);
    float4 mo = make_float4(s.x * inv, s.y * inv, s.z * inv, s.w * inv);
    float4 xo = (deg > 0) ? mx : make_float4(0.f, 0.f, 0.f, 0.f);
    ((float4*)(meanout + (size_t)warp * DD))[lane] = mo;
    ((float4*)(maxout  + (size_t)warp * DD))[lane] = xo;
}

// ---------------- mixed epilogue: normalize + relu + weighted k-sum -----------
__global__ void k_combine(const float* __restrict__ y, const float* __restrict__ stats,
                          const float* __restrict__ wrow, const float* __restrict__ gg,
                          const float* __restrict__ be, float* __restrict__ out,
                          int n, int accum) {
    int idx = blockIdx.x * blockDim.x + threadIdx.x;
    int total = n * DD;
    if (idx >= total) return;
    int d = idx & (DD - 1);
    float fn = (float)n;
    float acc = 0.f;
    #pragma unroll
    for (int k = 0; k < 3; k++) {
        float mu  = stats[k * DD + d] / fn;
        float var = stats[3 * DD + k * DD + d] / fn - mu * mu;
        float rs  = rsqrtf(var + EPSLN);
        float v = y[(size_t)k * n * DD + idx];
        float t = (v - mu) * rs * gg[k * DD + d] + be[k * DD + d];
        t = fmaxf(t, 0.f);
        acc += wrow[k] * t;
    }
    out[idx] = accum ? (out[idx] + acc) : acc;
}

// ---------------- final column-norm + relu ------------------------------------
__global__ void k_finalnorm(const float* __restrict__ h, const float* __restrict__ stats,
                            const float* __restrict__ gc, const float* __restrict__ bec,
                            float* __restrict__ out, int n) {
    int idx = blockIdx.x * blockDim.x + threadIdx.x;
    int total = n * DD;
    if (idx >= total) return;
    int d = idx & (DD - 1);
    float fn = (float)n;
    float mu  = stats[d] / fn;
    float var = stats[3 * DD + d] / fn - mu * mu;
    float rs  = rsqrtf(var + EPSLN);
    float v = (h[idx] - mu) * rs * gc[d] + bec[d];
    out[idx] = fmaxf(v, 0.f);
}

// ---------------- host orchestration ------------------------------------------
extern "C" void kernel_launch(void* const* d_in, const int* in_sizes, int n_in,
                              void* d_out, int out_size) {
    const float* src_emb = (const float*)d_in[0];
    const float* hr      = (const float*)d_in[1];
    const int*   esrc    = (const int*)d_in[2];
    const int*   edst    = (const int*)d_in[3];
    const float* w_zero  = (const float*)d_in[4];
    const float* w_first = (const float*)d_in[5];
    const float* w_mid   = (const float*)d_in[6];
    const float* w_last  = (const float*)d_in[7];
    const float* W_zero  = (const float*)d_in[8];
    const float* b_zero  = (const float*)d_in[9];
    const float* g_zeroP = (const float*)d_in[10];
    const float* be_zero = (const float*)d_in[11];
    const float* W_first = (const float*)d_in[12];
    const float* b_first = (const float*)d_in[13];
    const float* g_firstP= (const float*)d_in[14];
    const float* be_first= (const float*)d_in[15];
    const float* W_mid   = (const float*)d_in[16];
    const float* b_mid   = (const float*)d_in[17];
    const float* g_midP  = (const float*)d_in[18];
    const float* be_mid  = (const float*)d_in[19];
    const float* W_last  = (const float*)d_in[20];
    const float* b_last  = (const float*)d_in[21];
    const float* g_lastP = (const float*)d_in[22];
    const float* be_last = (const float*)d_in[23];
    const float* W_cat   = (const float*)d_in[24];
    const float* b_cat   = (const float*)d_in[25];
    const float* g_cat   = (const float*)d_in[26];
    const float* be_cat  = (const float*)d_in[27];

    int n = in_sizes[0] / DD;
    int e = in_sizes[2];

    float *yb, *hin, *s0, *s1, *m0, *m1, *sl, *mean, *mx, *statsA;
    int *deg, *rowptr, *cursor, *ssrc, *bsums;
    __nv_bfloat16* wpre;
    cudaGetSymbolAddress((void**)&yb, g_y);
    cudaGetSymbolAddress((void**)&hin, g_hin);
    cudaGetSymbolAddress((void**)&s0, g_s0);
    cudaGetSymbolAddress((void**)&s1, g_s1);
    cudaGetSymbolAddress((void**)&m0, g_m0);
    cudaGetSymbolAddress((void**)&m1, g_m1);
    cudaGetSymbolAddress((void**)&sl, g_slast);
    cudaGetSymbolAddress((void**)&mean, g_mean);
    cudaGetSymbolAddress((void**)&mx, g_max);
    cudaGetSymbolAddress((void**)&statsA, g_statsA);
    cudaGetSymbolAddress((void**)&deg, g_deg);
    cudaGetSymbolAddress((void**)&rowptr, g_rowptr);
    cudaGetSymbolAddress((void**)&cursor, g_cursor);
    cudaGetSymbolAddress((void**)&ssrc, g_ssrc);
    cudaGetSymbolAddress((void**)&bsums, g_bsums);
    cudaGetSymbolAddress((void**)&wpre, g_wpre);

    cudaFuncSetAttribute(k_gemm_mma, cudaFuncAttributeMaxDynamicSharedMemorySize, SMEM_MMA);

    int total = n * DD;
    size_t ystride = (size_t)n * DD;
    int gtiles = (n + 127) / 128;
    int ew_grid = (total + 255) / 256;
    int agg_grid = (n + 7) / 8;
    int eb = (e + 255) / 256;
    int nb1024 = (n + 1023) / 1024;

    // ---- weight prep (stats slots zeroed in first launch) ----
    k_wprep<<<3 * 8, 256>>>(W_zero,  wpre + 0L  * 32768, statsA, 9 * 768);
    k_wprep<<<9 * 8, 256>>>(W_first, wpre + 3L  * 32768, nullptr, 0);
    k_wprep<<<6 * 8, 256>>>(W_mid,   wpre + 12L * 32768, nullptr, 0);
    k_wprep<<<6 * 8, 256>>>(W_last,  wpre + 18L * 32768, nullptr, 0);
    k_wprep<<<3 * 8, 256>>>(W_cat,   wpre + 24L * 32768, nullptr, 0);

    int slot = 0;
    auto run_mixed = [&](const float* x0, const float* x1, const float* x2,
                         int opmat, const float* B, const float* G, const float* BE,
                         const float* wrow, float* out, int accum, int premode) {
        float* st = statsA + (size_t)slot * 768;
        slot++;
        k_gemm_mma<<<dim3(gtiles, 1, 3), 256, SMEM_MMA>>>(
            x0, x1, x2, wpre + (size_t)opmat * 32768, B, yb, st, n, ystride, 0, premode);
        k_combine<<<ew_grid, 256>>>(yb, st, wrow, G, BE, out, n, accum);
    };

    // ---- zero op (pre fused into GEMM fill; launch index 5 = k_gemm_mma) ----
    run_mixed(src_emb, hr, nullptr, 0, b_zero, g_zeroP, be_zero, w_zero, hin, 0, 1);

    // ---- CSR build ----
    cudaMemsetAsync(deg, 0, (size_t)n * sizeof(int));
    k_hist<<<eb, 256>>>(edst, deg, e);
    k_scan_block<<<nb1024, 1024>>>(deg, cursor, bsums, n);
    k_scan_sums<<<1, 32>>>(bsums, nb1024);
    k_scan_fin<<<(n + 255) / 256, 256>>>(deg, cursor, bsums, rowptr, cursor, n, e);
    k_scatter<<<eb, 256>>>(esrc, edst, cursor, ssrc, e);

    // ---- first ops ----
    k_agg<<<agg_grid, 256>>>(hin, rowptr, ssrc, mean, mx, n);
    run_mixed(hin, mean, mx, 3, b_first + 0 * 3 * DD, g_firstP + 0 * 3 * DD,
              be_first + 0 * 3 * DD, w_first + 0 * 3, s0, 0, 0);
    run_mixed(hin, mean, mx, 6, b_first + 1 * 3 * DD, g_firstP + 1 * 3 * DD,
              be_first + 1 * 3 * DD, w_first + 1 * 3, s1, 0, 0);
    k_agg<<<agg_grid, 256>>>(s0, rowptr, ssrc, mean, mx, n);
    run_mixed(s0, mean, mx, 9, b_first + 2 * 3 * DD, g_firstP + 2 * 3 * DD,
              be_first + 2 * 3 * DD, w_first + 2 * 3, s1, 1, 0);

    // ---- middle ops ----
    run_mixed(s0, mean, mx, 12, b_mid + 0 * 3 * DD, g_midP + 0 * 3 * DD,
              be_mid + 0 * 3 * DD, w_mid + 0 * 3, m0, 0, 0);
    k_agg<<<agg_grid, 256>>>(s1, rowptr, ssrc, mean, mx, n);
    run_mixed(s1, mean, mx, 15, b_mid + 1 * 3 * DD, g_midP + 1 * 3 * DD,
              be_mid + 1 * 3 * DD, w_mid + 1 * 3, m1, 0, 0);

    // ---- last ops ----
    k_agg<<<agg_grid, 256>>>(m0, rowptr, ssrc, mean, mx, n);
    run_mixed(m0, mean, mx, 18, b_last + 0 * 3 * DD, g_lastP + 0 * 3 * DD,
              be_last + 0 * 3 * DD, w_last + 0 * 3, sl, 0, 0);
    k_agg<<<agg_grid, 256>>>(m1, rowptr, ssrc, mean, mx, n);
    run_mixed(m1, mean, mx, 21, b_last + 1 * 3 * DD, g_lastP + 1 * 3 * DD,
              be_last + 1 * 3 * DD, w_last + 1 * 3, sl, 1, 0);

    // ---- final: cat GEMM (3 K-chunks) + column-norm ----
    {
        float* st = statsA + (size_t)8 * 768;
        k_gemm_mma<<<dim3(gtiles, 1, 1), 256, SMEM_MMA>>>(
            m0, m1, sl, wpre + 24L * 32768, b_cat, yb, st, n, ystride, 1, 0);
        k_finalnorm<<<ew_grid, 256>>>(yb, st, g_cat, be_cat, (float*)d_out, n);
    }
}

// round 7
// speedup vs baseline: 1.6214x; 1.2069x over previous
#include <cuda_runtime.h>
#include <cuda_fp16.h>
#include <cstdint>
#include <math_constants.h>

#define NN 100000
#define EE 600000
#define DD 128
#define EPSLN 1e-5f
#define PADK 72    // smem row stride in halves for 64-col tiles (144B, conflict-free ldmatrix)

// ---------------- scratch (device globals) -------------------------------------
__device__ float g_y[3L * NN * DD];
__device__ float g_hin[(size_t)NN * DD];
__device__ float g_s0[(size_t)NN * DD];
__device__ float g_s1[(size_t)NN * DD];
__device__ float g_m0[(size_t)NN * DD];
__device__ float g_m1[(size_t)NN * DD];
__device__ float g_slast[(size_t)NN * DD];
__device__ float g_mean[(size_t)NN * DD];
__device__ float g_max[(size_t)NN * DD];
__device__ float g_statsA[9 * 2 * 3 * DD];   // 9 op slots x (sum, sumsq) x 3 x 128
__device__ int   g_deg[NN];
__device__ int   g_rowptr[NN + 1];
__device__ int   g_cursor[NN];
__device__ int   g_ssrc[EE];
__device__ int   g_bsums[256];
__device__ __half g_wpre[27L * 16384];   // per matrix: fp16 W^T [f*128+d]

// ---------------- helpers ------------------------------------------------------
__device__ __forceinline__ uint32_t smem_u32(const void* p) {
    uint32_t a;
    asm("{ .reg .u64 t; cvta.to.shared.u64 t, %1; cvt.u32.u64 %0, t; }" : "=r"(a) : "l"(p));
    return a;
}
__device__ __forceinline__ uint32_t pkh(__half a, __half b) {
    return (uint32_t)__half_as_ushort(a) | ((uint32_t)__half_as_ushort(b) << 16);
}
__device__ __forceinline__ void ldsm_x4(uint32_t& r0, uint32_t& r1, uint32_t& r2, uint32_t& r3,
                                        uint32_t addr) {
    asm volatile("ldmatrix.sync.aligned.m8n8.x4.shared.b16 {%0, %1, %2, %3}, [%4];"
                 : "=r"(r0), "=r"(r1), "=r"(r2), "=r"(r3) : "r"(addr));
}
__device__ __forceinline__ void mma16816h(float* c, const uint32_t* a, const uint32_t* b) {
    asm volatile(
        "mma.sync.aligned.m16n8k16.row.col.f32.f16.f16.f32 "
        "{%0, %1, %2, %3}, {%4, %5, %6, %7}, {%8, %9}, {%0, %1, %2, %3};"
        : "+f"(c[0]), "+f"(c[1]), "+f"(c[2]), "+f"(c[3])
        : "r"(a[0]), "r"(a[1]), "r"(a[2]), "r"(a[3]), "r"(b[0]), "r"(b[1]));
}
__device__ __forceinline__ void cpasync16(uint32_t saddr, const void* gaddr) {
    asm volatile("cp.async.cg.shared.global [%0], [%1], 16;" :: "r"(saddr), "l"(gaddr));
}
__device__ __forceinline__ void cpasync_waitall() {
    asm volatile("cp.async.commit_group;");
    asm volatile("cp.async.wait_group 0;");
}

// ---------------- weight prep: W[d][f] fp32 -> fp16 W^T[f][d] -------------------
__global__ void k_wprep(const float* __restrict__ W, __half* __restrict__ out,
                        float* statszero, int zn) {
    if (statszero && blockIdx.x == 0) {
        for (int i = threadIdx.x; i < zn; i += blockDim.x) statszero[i] = 0.f;
    }
    int m = blockIdx.x >> 3;
    int part = blockIdx.x & 7;
    const float* src = W + (size_t)m * 16384;
    __half* oh = out + (size_t)m * 16384;
    int base = part * 2048;
    for (int i = threadIdx.x; i < 2048; i += blockDim.x) {
        int idx = base + i;
        int d = idx >> 7, f = idx & 127;
        oh[f * 128 + d] = __float2half_rn(src[idx]);
    }
}

// ---------------- fp16 2-pass tensor GEMM + fused column stats ------------------
// y = x @ W^T: A = x split fp16 hi+lo (exact), B = fp16(W) (only error source).
// 256 threads, 8 warps 4x2, warp tile 32x64; K in two 64-chunks; 2 CTAs/SM.
#define TILE_HALVES (128 * PADK)             // 9216 halves = 18432 B
#define SMEM_MMA (3 * TILE_HALVES * 2 + 1024)

__global__ __launch_bounds__(256, 2) void k_gemm_mma(
    const float* __restrict__ x0, const float* __restrict__ x1, const float* __restrict__ x2,
    const __half* __restrict__ wpre, const float* __restrict__ bias,
    float* __restrict__ Y, float* __restrict__ stats, int n, size_t ystride,
    int catmode, int premode)
{
    extern __shared__ char sm[];
    __half* Ahi = (__half*)sm;
    __half* Alo = Ahi + TILE_HALVES;
    __half* Bh  = Alo + TILE_HALVES;
    float* ssum = (float*)(Bh + TILE_HALVES);
    float* ssq  = ssum + 128;

    int tid = threadIdx.x;
    int wid = tid >> 5, lane = tid & 31;
    int wm_ = wid >> 1, wn_ = wid & 1;     // 4x2 warp grid, 32x64 warp tile
    int kcand = catmode ? 0 : blockIdx.z;
    int nchunk = catmode ? 3 : 1;
    int row0 = blockIdx.x * 128;
    float* Yk = Y + (size_t)kcand * ystride;
    const float* bk = bias + kcand * DD;
    int so = kcand * DD;

    if (tid < 128) { ssum[tid] = 0.f; ssq[tid] = 0.f; }

    float c[2][8][4];
    #pragma unroll
    for (int i = 0; i < 2; i++)
        #pragma unroll
        for (int j = 0; j < 8; j++)
            #pragma unroll
            for (int q = 0; q < 4; q++) c[i][j][q] = 0.f;

    int a_row = wm_ * 32 + (lane & 15);
    int a_k8 = (lane >> 4) * 8;
    int b_f = wn_ * 64 + ((lane >> 4) << 3) + (lane & 7);
    int b_k8 = ((lane >> 3) & 1) * 8;
    uint32_t uAhi = smem_u32(Ahi), uAlo = smem_u32(Alo);
    uint32_t uBh = smem_u32(Bh);

    for (int c3 = 0; c3 < nchunk; c3++) {
        const float* X = catmode ? (c3 == 0 ? x0 : (c3 == 1 ? x1 : x2)) : x0;

        for (int ch = 0; ch < 2; ch++) {          // K chunks of 64
            if (c3 + ch > 0) __syncthreads();     // prior mma reads done before refill

            // B fill via cp.async: rows f 0..127, cols ch*64..+64 (fp16, single tile)
            {
                int f = tid >> 1, half2 = (tid & 1) * 4;  // 2 threads/row, 4 uint4 each
                uint32_t dst = uBh + (uint32_t)(f * PADK * 2) + (uint32_t)(half2 * 16);
                const char* sh = (const char*)wpre + ((size_t)(catmode ? c3 : kcand) * 16384
                                 + (size_t)f * 128 + ch * 64) * 2 + half2 * 16;
                #pragma unroll
                for (int q = 0; q < 4; q++) cpasync16(dst + q * 16, sh + q * 16);
            }
            // A convert fp32 -> fp16 hi/lo (cols ch*64..+64); optional fused pre-op
            {
                int row = tid >> 1, sg = tid & 1;
                int gr = row0 + row;
                __half* dh = Ahi + row * PADK + sg * 32;
                __half* dl = Alo + row * PADK + sg * 32;
                int cbase = ch * 64 + sg * 32;
                #pragma unroll
                for (int q = 0; q < 8; q++) {
                    float4 v = make_float4(0.f, 0.f, 0.f, 0.f);
                    if (gr < n) {
                        v = *(const float4*)(x0 + (size_t)gr * DD + cbase + q * 4);
                        if (premode && kcand > 0) {
                            float4 b = *(const float4*)(x1 + (size_t)gr * DD + cbase + q * 4);
                            if (kcand == 1) { v.x -= b.x; v.y -= b.y; v.z -= b.z; v.w -= b.w; }
                            else            { v.x *= b.x; v.y *= b.y; v.z *= b.z; v.w *= b.w; }
                        } else if (!premode && !catmode) {
                            if (kcand == 1) v = *(const float4*)(x1 + (size_t)gr * DD + cbase + q * 4);
                            else if (kcand == 2) v = *(const float4*)(x2 + (size_t)gr * DD + cbase + q * 4);
                        } else if (catmode) {
                            v = *(const float4*)(X + (size_t)gr * DD + cbase + q * 4);
                        }
                    }
                    __half h0 = __float2half_rn(v.x), h1 = __float2half_rn(v.y);
                    __half h2 = __float2half_rn(v.z), h3 = __float2half_rn(v.w);
                    __half l0 = __float2half_rn(v.x - __half2float(h0));
                    __half l1 = __float2half_rn(v.y - __half2float(h1));
                    __half l2 = __float2half_rn(v.z - __half2float(h2));
                    __half l3 = __float2half_rn(v.w - __half2float(h3));
                    *(uint2*)(dh + q * 4) = make_uint2(pkh(h0, h1), pkh(h2, h3));
                    *(uint2*)(dl + q * 4) = make_uint2(pkh(l0, l1), pkh(l2, l3));
                }
            }
            cpasync_waitall();
            __syncthreads();

            // 2 fp16 passes per k-step: hi_a*b + lo_a*b (B regs reused)
            #pragma unroll
            for (int k = 0; k < 4; k++) {
                uint32_t ah[2][4], al[2][4];
                #pragma unroll
                for (int mt = 0; mt < 2; mt++) {
                    uint32_t off = (uint32_t)(((a_row + mt * 16) * PADK + k * 16 + a_k8) * 2);
                    ldsm_x4(ah[mt][0], ah[mt][1], ah[mt][2], ah[mt][3], uAhi + off);
                    ldsm_x4(al[mt][0], al[mt][1], al[mt][2], al[mt][3], uAlo + off);
                }
                uint32_t b[4][4];
                #pragma unroll
                for (int p = 0; p < 4; p++) {
                    uint32_t addr = uBh + (uint32_t)(((b_f + p * 16) * PADK + k * 16 + b_k8) * 2);
                    ldsm_x4(b[p][0], b[p][1], b[p][2], b[p][3], addr);
                }
                #pragma unroll
                for (int mt = 0; mt < 2; mt++)
                    #pragma unroll
                    for (int nt = 0; nt < 8; nt++) {
                        mma16816h(c[mt][nt], ah[mt], &b[nt >> 1][(nt & 1) * 2]);
                        mma16816h(c[mt][nt], al[mt], &b[nt >> 1][(nt & 1) * 2]);
                    }
            }
        }
    }

    // ---------------- epilogue: bias, store Y, fused column stats ---------------
    int erow = lane >> 2, ecp = lane & 3;
    float2 bb[8];
    #pragma unroll
    for (int nt = 0; nt < 8; nt++)
        bb[nt] = *(const float2*)(bk + wn_ * 64 + nt * 8 + ecp * 2);

    float lsum[16], lsq[16];
    #pragma unroll
    for (int j = 0; j < 16; j++) { lsum[j] = 0.f; lsq[j] = 0.f; }

    #pragma unroll
    for (int mt = 0; mt < 2; mt++) {
        int r0g = row0 + wm_ * 32 + mt * 16 + erow;
        int r1g = r0g + 8;
        #pragma unroll
        for (int nt = 0; nt < 8; nt++) {
            int cbase = wn_ * 64 + nt * 8 + ecp * 2;
            float v00 = c[mt][nt][0] + bb[nt].x;
            float v01 = c[mt][nt][1] + bb[nt].y;
            float v10 = c[mt][nt][2] + bb[nt].x;
            float v11 = c[mt][nt][3] + bb[nt].y;
            if (r0g < n) {
                *(float2*)(Yk + (size_t)r0g * DD + cbase) = make_float2(v00, v01);
                lsum[nt * 2]     += v00; lsq[nt * 2]     += v00 * v00;
                lsum[nt * 2 + 1] += v01; lsq[nt * 2 + 1] += v01 * v01;
            }
            if (r1g < n) {
                *(float2*)(Yk + (size_t)r1g * DD + cbase) = make_float2(v10, v11);
                lsum[nt * 2]     += v10; lsq[nt * 2]     += v10 * v10;
                lsum[nt * 2 + 1] += v11; lsq[nt * 2 + 1] += v11 * v11;
            }
        }
    }
    #pragma unroll
    for (int nt = 0; nt < 8; nt++) {
        int cbase = wn_ * 64 + nt * 8 + ecp * 2;
        atomicAdd(&ssum[cbase],     lsum[nt * 2]);
        atomicAdd(&ssq[cbase],      lsq[nt * 2]);
        atomicAdd(&ssum[cbase + 1], lsum[nt * 2 + 1]);
        atomicAdd(&ssq[cbase + 1],  lsq[nt * 2 + 1]);
    }
    __syncthreads();
    if (tid < 128) {
        atomicAdd(&stats[so + tid], ssum[tid]);
        atomicAdd(&stats[3 * DD + so + tid], ssq[tid]);
    }
}

// ---------------- CSR build ---------------------------------------------------
__global__ void k_hist(const int* __restrict__ dst, int* deg, int e) {
    int i = blockIdx.x * blockDim.x + threadIdx.x;
    if (i < e) atomicAdd(&deg[dst[i]], 1);
}
__global__ void k_scan_block(const int* __restrict__ deg, int* incl, int* bsums, int n) {
    __shared__ int sh[1024];
    int i = blockIdx.x * 1024 + threadIdx.x;
    int v = (i < n) ? deg[i] : 0;
    sh[threadIdx.x] = v;
    __syncthreads();
    for (int off = 1; off < 1024; off <<= 1) {
        int t = (threadIdx.x >= off) ? sh[threadIdx.x - off] : 0;
        __syncthreads();
        sh[threadIdx.x] += t;
        __syncthreads();
    }
    if (i < n) incl[i] = sh[threadIdx.x];
    if (threadIdx.x == 1023) bsums[blockIdx.x] = sh[1023];
}
__global__ void k_scan_sums(int* bsums, int nb) {
    if (threadIdx.x == 0 && blockIdx.x == 0) {
        int run = 0;
        for (int i = 0; i < nb; i++) { int t = bsums[i]; bsums[i] = run; run += t; }
    }
}
__global__ void k_scan_fin(const int* __restrict__ deg, const int* __restrict__ incl,
                           const int* __restrict__ bsums, int* rowptr, int* cursor, int n, int e) {
    int i = blockIdx.x * blockDim.x + threadIdx.x;
    if (i < n) {
        int ex = incl[i] - deg[i] + bsums[i >> 10];
        rowptr[i] = ex;
        cursor[i] = ex;
        if (i == n - 1) rowptr[n] = e;
    }
}
__global__ void k_scatter(const int* __restrict__ src, const int* __restrict__ dst,
                          int* cursor, int* ssrc, int e) {
    int i = blockIdx.x * blockDim.x + threadIdx.x;
    if (i < e) {
        int p = atomicAdd(&cursor[dst[i]], 1);
        ssrc[p] = src[i];
    }
}

// ---------------- graph aggregation (mean + max), warp per node ---------------
__global__ void k_agg(const float* __restrict__ h, const int* __restrict__ rowptr,
                      const int* __restrict__ ssrc, float* __restrict__ meanout,
                      float* __restrict__ maxout, int n) {
    int warp = (blockIdx.x * blockDim.x + threadIdx.x) >> 5;
    int lane = threadIdx.x & 31;
    if (warp >= n) return;
    int beg = rowptr[warp], end = rowptr[warp + 1];
    float4 s  = make_float4(0.f, 0.f, 0.f, 0.f);
    float4 mx = make_float4(-CUDART_INF_F, -CUDART_INF_F, -CUDART_INF_F, -CUDART_INF_F);
    for (int i = beg; i < end; i++) {
        int src = ssrc[i];
        float4 v = ((const float4*)(h + (size_t)src * DD))[lane];
        s.x += v.x; s.y += v.y; s.z += v.z; s.w += v.w;
        mx.x = fmaxf(mx.x, v.x); mx.y = fmaxf(mx.y, v.y);
        mx.z = fmaxf(mx.z, v.z); mx.w = fmaxf(mx.w, v.w);
    }
    int deg = end - beg;
    float inv = 1.0f / (float)max(deg, 1);
    float4 mo = make_float4(s.x * inv, s.y * inv, s.z * inv, s.w * inv);
    float4 xo = (deg > 0) ? mx : make_float4(0.f, 0.f, 0.f, 0.f);
    ((float4*)(meanout + (size_t)warp * DD))[lane] = mo;
    ((float4*)(maxout  + (size_t)warp * DD))[lane] = xo;
}

// ---------------- mixed epilogue: normalize + relu + weighted k-sum (float4) ---
__global__ void k_combine(const float* __restrict__ y, const float* __restrict__ stats,
                          const float* __restrict__ wrow, const float* __restrict__ gg,
                          const float* __restrict__ be, float* __restrict__ out,
                          int n, int accum) {
    int i4 = blockIdx.x * blockDim.x + threadIdx.x;
    int total4 = (n * DD) >> 2;
    if (i4 >= total4) return;
    int d0 = (i4 << 2) & (DD - 1);
    float fn = (float)n;
    float4 acc = make_float4(0.f, 0.f, 0.f, 0.f);
    #pragma unroll
    for (int k = 0; k < 3; k++) {
        float wk = wrow[k];
        float4 v = ((const float4*)(y + (size_t)k * n * DD))[i4];
        #pragma unroll
        for (int j = 0; j < 4; j++) {
            int d = d0 + j;
            float mu  = stats[k * DD + d] / fn;
            float var = stats[3 * DD + k * DD + d] / fn - mu * mu;
            float rs  = rsqrtf(var + EPSLN);
            float vv = (&v.x)[j];
            float t = (vv - mu) * rs * gg[k * DD + d] + be[k * DD + d];
            (&acc.x)[j] += wk * fmaxf(t, 0.f);
        }
    }
    if (accum) {
        float4 o = ((float4*)out)[i4];
        acc.x += o.x; acc.y += o.y; acc.z += o.z; acc.w += o.w;
    }
    ((float4*)out)[i4] = acc;
}

// ---------------- final column-norm + relu ------------------------------------
__global__ void k_finalnorm(const float* __restrict__ h, const float* __restrict__ stats,
                            const float* __restrict__ gc, const float* __restrict__ bec,
                            float* __restrict__ out, int n) {
    int idx = blockIdx.x * blockDim.x + threadIdx.x;
    int total = n * DD;
    if (idx >= total) return;
    int d = idx & (DD - 1);
    float fn = (float)n;
    float mu  = stats[d] / fn;
    float var = stats[3 * DD + d] / fn - mu * mu;
    float rs  = rsqrtf(var + EPSLN);
    float v = (h[idx] - mu) * rs * gc[d] + bec[d];
    out[idx] = fmaxf(v, 0.f);
}

// ---------------- host orchestration ------------------------------------------
extern "C" void kernel_launch(void* const* d_in, const int* in_sizes, int n_in,
                              void* d_out, int out_size) {
    const float* src_emb = (const float*)d_in[0];
    const float* hr      = (const float*)d_in[1];
    const int*   esrc    = (const int*)d_in[2];
    const int*   edst    = (const int*)d_in[3];
    const float* w_zero  = (const float*)d_in[4];
    const float* w_first = (const float*)d_in[5];
    const float* w_mid   = (const float*)d_in[6];
    const float* w_last  = (const float*)d_in[7];
    const float* W_zero  = (const float*)d_in[8];
    const float* b_zero  = (const float*)d_in[9];
    const float* g_zeroP = (const float*)d_in[10];
    const float* be_zero = (const float*)d_in[11];
    const float* W_first = (const float*)d_in[12];
    const float* b_first = (const float*)d_in[13];
    const float* g_firstP= (const float*)d_in[14];
    const float* be_first= (const float*)d_in[15];
    const float* W_mid   = (const float*)d_in[16];
    const float* b_mid   = (const float*)d_in[17];
    const float* g_midP  = (const float*)d_in[18];
    const float* be_mid  = (const float*)d_in[19];
    const float* W_last  = (const float*)d_in[20];
    const float* b_last  = (const float*)d_in[21];
    const float* g_lastP = (const float*)d_in[22];
    const float* be_last = (const float*)d_in[23];
    const float* W_cat   = (const float*)d_in[24];
    const float* b_cat   = (const float*)d_in[25];
    const float* g_cat   = (const float*)d_in[26];
    const float* be_cat  = (const float*)d_in[27];

    int n = in_sizes[0] / DD;
    int e = in_sizes[2];

    float *yb, *hin, *s0, *s1, *m0, *m1, *sl, *mean, *mx, *statsA;
    int *deg, *rowptr, *cursor, *ssrc, *bsums;
    __half* wpre;
    cudaGetSymbolAddress((void**)&yb, g_y);
    cudaGetSymbolAddress((void**)&hin, g_hin);
    cudaGetSymbolAddress((void**)&s0, g_s0);
    cudaGetSymbolAddress((void**)&s1, g_s1);
    cudaGetSymbolAddress((void**)&m0, g_m0);
    cudaGetSymbolAddress((void**)&m1, g_m1);
    cudaGetSymbolAddress((void**)&sl, g_slast);
    cudaGetSymbolAddress((void**)&mean, g_mean);
    cudaGetSymbolAddress((void**)&mx, g_max);
    cudaGetSymbolAddress((void**)&statsA, g_statsA);
    cudaGetSymbolAddress((void**)&deg, g_deg);
    cudaGetSymbolAddress((void**)&rowptr, g_rowptr);
    cudaGetSymbolAddress((void**)&cursor, g_cursor);
    cudaGetSymbolAddress((void**)&ssrc, g_ssrc);
    cudaGetSymbolAddress((void**)&bsums, g_bsums);
    cudaGetSymbolAddress((void**)&wpre, g_wpre);

    cudaFuncSetAttribute(k_gemm_mma, cudaFuncAttributeMaxDynamicSharedMemorySize, SMEM_MMA);

    int total = n * DD;
    size_t ystride = (size_t)n * DD;
    int gtiles = (n + 127) / 128;
    int ew_grid = (total + 255) / 256;
    int ew_grid4 = (total / 4 + 255) / 256;
    int agg_grid = (n + 7) / 8;
    int eb = (e + 255) / 256;
    int nb1024 = (n + 1023) / 1024;

    // ---- weight prep (stats slots zeroed in first launch) ----
    k_wprep<<<3 * 8, 256>>>(W_zero,  wpre + 0L  * 16384, statsA, 9 * 768);
    k_wprep<<<9 * 8, 256>>>(W_first, wpre + 3L  * 16384, nullptr, 0);
    k_wprep<<<6 * 8, 256>>>(W_mid,   wpre + 12L * 16384, nullptr, 0);
    k_wprep<<<6 * 8, 256>>>(W_last,  wpre + 18L * 16384, nullptr, 0);
    k_wprep<<<3 * 8, 256>>>(W_cat,   wpre + 24L * 16384, nullptr, 0);

    int slot = 0;
    auto run_mixed = [&](const float* x0, const float* x1, const float* x2,
                         int opmat, const float* B, const float* G, const float* BE,
                         const float* wrow, float* out, int accum, int premode) {
        float* st = statsA + (size_t)slot * 768;
        slot++;
        k_gemm_mma<<<dim3(gtiles, 1, 3), 256, SMEM_MMA>>>(
            x0, x1, x2, wpre + (size_t)opmat * 16384, B, yb, st, n, ystride, 0, premode);
        k_combine<<<ew_grid4, 256>>>(yb, st, wrow, G, BE, out, n, accum);
    };

    // ---- zero op (pre fused into GEMM fill) ----
    run_mixed(src_emb, hr, nullptr, 0, b_zero, g_zeroP, be_zero, w_zero, hin, 0, 1);

    // ---- CSR build ----
    cudaMemsetAsync(deg, 0, (size_t)n * sizeof(int));
    k_hist<<<eb, 256>>>(edst, deg, e);
    k_scan_block<<<nb1024, 1024>>>(deg, cursor, bsums, n);
    k_scan_sums<<<1, 32>>>(bsums, nb1024);
    k_scan_fin<<<(n + 255) / 256, 256>>>(deg, cursor, bsums, rowptr, cursor, n, e);
    k_scatter<<<eb, 256>>>(esrc, edst, cursor, ssrc, e);

    // ---- first ops ----
    k_agg<<<agg_grid, 256>>>(hin, rowptr, ssrc, mean, mx, n);
    run_mixed(hin, mean, mx, 3, b_first + 0 * 3 * DD, g_firstP + 0 * 3 * DD,
              be_first + 0 * 3 * DD, w_first + 0 * 3, s0, 0, 0);
    run_mixed(hin, mean, mx, 6, b_first + 1 * 3 * DD, g_firstP + 1 * 3 * DD,
              be_first + 1 * 3 * DD, w_first + 1 * 3, s1, 0, 0);
    k_agg<<<agg_grid, 256>>>(s0, rowptr, ssrc, mean, mx, n);
    run_mixed(s0, mean, mx, 9, b_first + 2 * 3 * DD, g_firstP + 2 * 3 * DD,
              be_first + 2 * 3 * DD, w_first + 2 * 3, s1, 1, 0);

    // ---- middle ops ----
    run_mixed(s0, mean, mx, 12, b_mid + 0 * 3 * DD, g_midP + 0 * 3 * DD,
              be_mid + 0 * 3 * DD, w_mid + 0 * 3, m0, 0, 0);
    k_agg<<<agg_grid, 256>>>(s1, rowptr, ssrc, mean, mx, n);
    run_mixed(s1, mean, mx, 15, b_mid + 1 * 3 * DD, g_midP + 1 * 3 * DD,
              be_mid + 1 * 3 * DD, w_mid + 1 * 3, m1, 0, 0);

    // ---- last ops ----
    k_agg<<<agg_grid, 256>>>(m0, rowptr, ssrc, mean, mx, n);
    run_mixed(m0, mean, mx, 18, b_last + 0 * 3 * DD, g_lastP + 0 * 3 * DD,
              be_last + 0 * 3 * DD, w_last + 0 * 3, sl, 0, 0);
    k_agg<<<agg_grid, 256>>>(m1, rowptr, ssrc, mean, mx, n);
    run_mixed(m1, mean, mx, 21, b_last + 1 * 3 * DD, g_lastP + 1 * 3 * DD,
              be_last + 1 * 3 * DD, w_last + 1 * 3, sl, 1, 0);

    // ---- final: cat GEMM (3 K-chunks) + column-norm ----
    {
        float* st = statsA + (size_t)8 * 768;
        k_gemm_mma<<<dim3(gtiles, 1, 1), 256, SMEM_MMA>>>(
            m0, m1, sl, wpre + 24L * 16384, b_cat, yb, st, n, ystride, 1, 0);
        k_finalnorm<<<ew_grid, 256>>>(yb, st, g_cat, be_cat, (float*)d_out, n);
    }
}